// round 1
// baseline (speedup 1.0000x reference)
#include <cuda_runtime.h>
#include <cuda_bf16.h>
#include <math.h>

#define B_ 256
#define L_ 3000
#define NCH_ 4
#define NQ_ 8
#define NL_ 2
#define FW_ 128
#define NCLS_ 5

// ---------------- scratch buffers (device globals; no allocation allowed) ----------------
__device__ float g_buf1[B_ * 32 * 3000];   // conv1 out
__device__ float g_buf2[B_ * 64 * 750];    // conv2+pool out
__device__ float g_buf3[B_ * 128 * 187];   // conv3+pool out
__device__ float g_buf4[B_ * 128 * 187];   // conv4 out
__device__ float g_feat[B_ * 128];         // mean over L
__device__ float g_ang[B_ * NQ_];          // angles

// ---------------- fused conv1d(k=7,pad=3) + BN(eval) + ReLU + optional maxpool4 ----------
// Block: 128 threads (4 warps). Each block: one batch b, 128 consecutive conv positions.
// Warp -> COUT/4 output channels; lane -> 4 consecutive conv positions (float4 smem loads).
template<int CIN, int COUT, int POOL>
__global__ void conv_bn_relu_pool(
    const float* __restrict__ in, const float* __restrict__ w,
    const float* __restrict__ cb, const float* __restrict__ bng, const float* __restrict__ bnb,
    float* __restrict__ out, int Lin, int Lconv, int Lpool)
{
    constexpr int TLC = 128;         // conv positions per block
    constexpr int RS  = TLC + 8;     // smem row stride (floats), 16B-aligned rows
    extern __shared__ float s_in[];  // CIN * RS floats

    const int b     = blockIdx.y;
    const int tile0 = blockIdx.x * TLC;
    const int tid   = threadIdx.x;

    // load input tile: positions tile0-3 .. tile0+TLC+2 -> s_in idx 0..TLC+5 (zero padded)
    const float* inb = in + (size_t)b * CIN * Lin;
    for (int idx = tid; idx < CIN * (TLC + 6); idx += blockDim.x) {
        int ci = idx / (TLC + 6);
        int j  = idx - ci * (TLC + 6);
        int p  = tile0 - 3 + j;
        s_in[ci * RS + j] = (p >= 0 && p < Lin) ? inb[ci * Lin + p] : 0.0f;
    }
    __syncthreads();

    const int warp = tid >> 5;
    const int lane = tid & 31;
    const int l0   = lane * 4;                 // relative conv position of this thread
    constexpr int CO_PER_WARP = COUT / 4;
    const float inv = rsqrtf(1.0f + 1e-5f);

    for (int coi = 0; coi < CO_PER_WARP; coi++) {
        const int co = warp * CO_PER_WARP + coi;
        float acc0 = 0.f, acc1 = 0.f, acc2 = 0.f, acc3 = 0.f;
        const float* wrow = w + (size_t)co * CIN * 7;
        #pragma unroll 4
        for (int ci = 0; ci < CIN; ci++) {
            const float* srow = s_in + ci * RS + l0;
            float4 xa = *(const float4*)(srow);
            float4 xb = *(const float4*)(srow + 4);
            float4 xc = *(const float4*)(srow + 8);
            float xv[10] = {xa.x, xa.y, xa.z, xa.w, xb.x, xb.y, xb.z, xb.w, xc.x, xc.y};
            const float* wp = wrow + ci * 7;
            #pragma unroll
            for (int k = 0; k < 7; k++) {
                float wk = wp[k];
                acc0 = fmaf(wk, xv[k + 0], acc0);
                acc1 = fmaf(wk, xv[k + 1], acc1);
                acc2 = fmaf(wk, xv[k + 2], acc2);
                acc3 = fmaf(wk, xv[k + 3], acc3);
            }
        }
        const float sc = bng[co] * inv;
        const float be = bnb[co];
        const float bi = cb[co];
        float y0 = fmaxf((acc0 + bi) * sc + be, 0.f);
        float y1 = fmaxf((acc1 + bi) * sc + be, 0.f);
        float y2 = fmaxf((acc2 + bi) * sc + be, 0.f);
        float y3 = fmaxf((acc3 + bi) * sc + be, 0.f);
        if (POOL == 4) {
            int pi = (tile0 >> 2) + lane;
            if (pi < Lpool) {
                float m = fmaxf(fmaxf(y0, y1), fmaxf(y2, y3));
                out[((size_t)b * COUT + co) * Lpool + pi] = m;
            }
        } else {
            float ys[4] = {y0, y1, y2, y3};
            #pragma unroll
            for (int r = 0; r < 4; r++) {
                int pos = tile0 + l0 + r;
                if (pos < Lconv) out[((size_t)b * COUT + co) * Lconv + pos] = ys[r];
            }
        }
    }
}

// ---------------- mean over last dim: (B,128,L) -> (B,128) ----------------
__global__ void mean_kernel(const float* __restrict__ in, float* __restrict__ out, int C, int L)
{
    int b = blockIdx.x;
    int warp = threadIdx.x >> 5, lane = threadIdx.x & 31;
    int cpw = C / 8;  // 8 warps
    for (int c = warp * cpw; c < (warp + 1) * cpw; c++) {
        const float* row = in + ((size_t)b * C + c) * L;
        float s = 0.f;
        for (int l = lane; l < L; l += 32) s += row[l];
        #pragma unroll
        for (int o = 16; o; o >>= 1) s += __shfl_down_sync(0xffffffffu, s, o);
        if (lane == 0) out[b * C + c] = s / (float)L;
    }
}

// ---------------- fc(128->128)+relu, ang(128->8), angles = pi*tanh ----------------
__global__ void head_kernel(const float* __restrict__ feat,
                            const float* __restrict__ fcw, const float* __restrict__ fcb,
                            const float* __restrict__ angw, const float* __restrict__ angb,
                            float* __restrict__ ang)
{
    int b = blockIdx.x, tid = threadIdx.x;  // 128 threads
    __shared__ float f[128];
    __shared__ float h[128];
    f[tid] = feat[b * 128 + tid];
    __syncthreads();
    float a = fcb[tid];
    const float* wr = fcw + tid * 128;
    #pragma unroll 8
    for (int k = 0; k < 128; k++) a = fmaf(wr[k], f[k], a);
    h[tid] = fmaxf(a, 0.f);
    __syncthreads();
    if (tid < NQ_) {
        float r = angb[tid];
        const float* ar = angw + tid * 128;
        #pragma unroll 8
        for (int k = 0; k < 128; k++) r = fmaf(ar[k], h[k], r);
        ang[b * NQ_ + tid] = 3.14159265358979323846f * tanhf(r);
    }
}

// ---------------- 8-qubit statevector sim + PauliZ + MLP head ----------------
__device__ __forceinline__ float2 cmul(float2 a, float2 b) {
    return make_float2(a.x * b.x - a.y * b.y, a.x * b.y + a.y * b.x);
}
__device__ __forceinline__ float2 cadd(float2 a, float2 b) {
    return make_float2(a.x + b.x, a.y + b.y);
}

__global__ void qsim_kernel(const float* __restrict__ ang, const float* __restrict__ qw,
                            const float* __restrict__ h1w, const float* __restrict__ h1b,
                            const float* __restrict__ h2w, const float* __restrict__ h2b,
                            float* __restrict__ out)
{
    int b = blockIdx.x, i = threadIdx.x;  // 256 threads, one amplitude each
    __shared__ float2 st[256];
    st[i] = make_float2(i == 0 ? 1.f : 0.f, 0.f);
    __syncthreads();

    // AngleEmbedding: RY(angles[b][w]) on wire w (wire 0 = MSB)
    for (int wq = 0; wq < NQ_; wq++) {
        int m = 1 << (7 - wq);
        float a = 0.5f * ang[b * NQ_ + wq];
        float c = cosf(a), s = sinf(a);
        if ((i & m) == 0) {
            float2 a0 = st[i], a1 = st[i | m];
            st[i]     = make_float2(c * a0.x - s * a1.x, c * a0.y - s * a1.y);
            st[i | m] = make_float2(s * a0.x + c * a1.x, s * a0.y + c * a1.y);
        }
        __syncthreads();
    }

    // StronglyEntanglingLayers
    for (int l = 0; l < NL_; l++) {
        for (int wq = 0; wq < NQ_; wq++) {
            int m = 1 << (7 - wq);
            const float* p = qw + (l * NQ_ + wq) * 3;
            float phi = p[0], th = p[1], om = p[2];
            float cm = cosf(0.5f * th), sm = sinf(0.5f * th);
            float hpo = 0.5f * (phi + om), hpm = 0.5f * (phi - om);
            float2 m00 = make_float2( cm * cosf(hpo), -cm * sinf(hpo));
            float2 m01 = make_float2(-sm * cosf(hpm), -sm * sinf(hpm));
            float2 m10 = make_float2( sm * cosf(hpm), -sm * sinf(hpm));
            float2 m11 = make_float2( cm * cosf(hpo),  cm * sinf(hpo));
            if ((i & m) == 0) {
                float2 a0 = st[i], a1 = st[i | m];
                st[i]     = cadd(cmul(m00, a0), cmul(m01, a1));
                st[i | m] = cadd(cmul(m10, a0), cmul(m11, a1));
            }
            __syncthreads();
        }
        int r = (l % (NQ_ - 1)) + 1;
        for (int q = 0; q < NQ_; q++) {
            int c = q, t = (q + r) & 7;
            int mc = 1 << (7 - c), mt = 1 << (7 - t);
            if ((i & mc) && !(i & mt)) {
                float2 tmp = st[i];
                st[i] = st[i | mt];
                st[i | mt] = tmp;
            }
            __syncthreads();
        }
    }

    __shared__ float pr[256];
    pr[i] = st[i].x * st[i].x + st[i].y * st[i].y;
    __syncthreads();

    __shared__ float z[NQ_];
    if (i < NQ_) {
        float s = 0.f;
        int sh = 7 - i;
        for (int j = 0; j < 256; j++) s += ((j >> sh) & 1) ? -pr[j] : pr[j];
        z[i] = s;
    }
    __syncthreads();

    __shared__ float h1[64];
    if (i < 64) {
        float a = h1b[i];
        #pragma unroll
        for (int k = 0; k < NQ_; k++) a = fmaf(h1w[i * NQ_ + k], z[k], a);
        h1[i] = fmaxf(a, 0.f);
    }
    __syncthreads();

    if (i < NCLS_) {
        float a = h2b[i];
        #pragma unroll 8
        for (int k = 0; k < 64; k++) a = fmaf(h2w[i * 64 + k], h1[k], a);
        out[b * NCLS_ + i] = a;
    }
}

// ---------------- launch ----------------
extern "C" void kernel_launch(void* const* d_in, const int* in_sizes, int n_in,
                              void* d_out, int out_size)
{
    const float* x       = (const float*)d_in[0];
    const float* conv1_w = (const float*)d_in[1];
    const float* conv1_b = (const float*)d_in[2];
    const float* bn1_g   = (const float*)d_in[3];
    const float* bn1_b   = (const float*)d_in[4];
    const float* conv2_w = (const float*)d_in[5];
    const float* conv2_b = (const float*)d_in[6];
    const float* bn2_g   = (const float*)d_in[7];
    const float* bn2_b   = (const float*)d_in[8];
    const float* conv3_w = (const float*)d_in[9];
    const float* conv3_b = (const float*)d_in[10];
    const float* bn3_g   = (const float*)d_in[11];
    const float* bn3_b   = (const float*)d_in[12];
    const float* conv4_w = (const float*)d_in[13];
    const float* conv4_b = (const float*)d_in[14];
    const float* bn4_g   = (const float*)d_in[15];
    const float* bn4_b   = (const float*)d_in[16];
    const float* fc_w    = (const float*)d_in[17];
    const float* fc_b    = (const float*)d_in[18];
    const float* ang_w   = (const float*)d_in[19];
    const float* ang_b   = (const float*)d_in[20];
    const float* qw      = (const float*)d_in[21];
    const float* h1_w    = (const float*)d_in[22];
    const float* h1_b    = (const float*)d_in[23];
    const float* h2_w    = (const float*)d_in[24];
    const float* h2_b    = (const float*)d_in[25];
    float* out = (float*)d_out;

    float *b1, *b2, *b3, *b4, *feat, *ang;
    cudaGetSymbolAddress((void**)&b1, g_buf1);
    cudaGetSymbolAddress((void**)&b2, g_buf2);
    cudaGetSymbolAddress((void**)&b3, g_buf3);
    cudaGetSymbolAddress((void**)&b4, g_buf4);
    cudaGetSymbolAddress((void**)&feat, g_feat);
    cudaGetSymbolAddress((void**)&ang, g_ang);

    constexpr int RS = 136;
    size_t sm1 = (size_t)4   * RS * 4;
    size_t sm2 = (size_t)32  * RS * 4;
    size_t sm3 = (size_t)64  * RS * 4;
    size_t sm4 = (size_t)128 * RS * 4;  // 69632 > 48KB

    cudaFuncSetAttribute(conv_bn_relu_pool<128, 128, 1>,
                         cudaFuncAttributeMaxDynamicSharedMemorySize, (int)sm4);
    cudaFuncSetAttribute(conv_bn_relu_pool<64, 128, 4>,
                         cudaFuncAttributeMaxDynamicSharedMemorySize, (int)sm3);

    // conv1: (B,4,3000) -> (B,32,3000)
    conv_bn_relu_pool<4, 32, 1><<<dim3(24, B_), 128, sm1>>>(
        x, conv1_w, conv1_b, bn1_g, bn1_b, b1, 3000, 3000, 0);
    // conv2 + pool4: -> (B,64,750)
    conv_bn_relu_pool<32, 64, 4><<<dim3(24, B_), 128, sm2>>>(
        b1, conv2_w, conv2_b, bn2_g, bn2_b, b2, 3000, 3000, 750);
    // conv3 + pool4: -> (B,128,187)
    conv_bn_relu_pool<64, 128, 4><<<dim3(6, B_), 128, sm3>>>(
        b2, conv3_w, conv3_b, bn3_g, bn3_b, b3, 750, 750, 187);
    // conv4: -> (B,128,187)
    conv_bn_relu_pool<128, 128, 1><<<dim3(2, B_), 128, sm4>>>(
        b3, conv4_w, conv4_b, bn4_g, bn4_b, b4, 187, 187, 0);
    // mean -> (B,128)
    mean_kernel<<<B_, 256>>>(b4, feat, 128, 187);
    // fc + ang head -> angles (B,8)
    head_kernel<<<B_, 128>>>(feat, fc_w, fc_b, ang_w, ang_b, ang);
    // quantum sim + final MLP -> (B,5)
    qsim_kernel<<<B_, 256>>>(ang, qw, h1_w, h1_b, h2_w, h2_b, out);
}

// round 2
// speedup vs baseline: 1.2019x; 1.2019x over previous
#include <cuda_runtime.h>
#include <cuda_bf16.h>
#include <math.h>

#define B_ 256
#define NQ_ 8
#define NL_ 2
#define NCLS_ 5

typedef unsigned long long ull;

// ---------------- scratch buffers ----------------
__device__ float g_buf1[B_ * 32 * 3000];   // conv1 out
__device__ float g_buf2[B_ * 64 * 750];    // conv2+pool out
__device__ float g_buf3[B_ * 128 * 187];   // conv3+pool out
__device__ float g_feat[B_ * 128];         // conv4+mean out
__device__ float g_ang[B_ * NQ_];          // angles

// prepacked weights: [(co*CIN+ci)*8 + k] as float2(w*sc, w*sc), k=7 zero-padded
__device__ float2 g_wp1[32 * 4 * 8];
__device__ float2 g_wp2[64 * 32 * 8];
__device__ float2 g_wp3[128 * 64 * 8];
__device__ float2 g_wp4[128 * 128 * 8];
__device__ float  g_bb1[32], g_bb2[64], g_bb3[128], g_bb4[128];

// ---------------- f32x2 helpers ----------------
__device__ __forceinline__ ull pack2(float lo, float hi) {
    ull r; asm("mov.b64 %0,{%1,%2};" : "=l"(r) : "f"(lo), "f"(hi)); return r;
}
__device__ __forceinline__ void unpack2(ull v, float& lo, float& hi) {
    asm("mov.b64 {%0,%1},%2;" : "=f"(lo), "=f"(hi) : "l"(v));
}
__device__ __forceinline__ void ffma2(ull& acc, ull a, ull b) {
    asm("fma.rn.f32x2 %0,%1,%2,%0;" : "+l"(acc) : "l"(a), "l"(b));
}

// ---------------- weight prepack: fold BN scale, dup pairs, pad k to 8 ------
__global__ void prep_kernel(const float* __restrict__ w, const float* __restrict__ cb,
                            const float* __restrict__ bng, const float* __restrict__ bnb,
                            float2* __restrict__ wp, float* __restrict__ bbo,
                            int CIN, int COUT)
{
    const float inv = rsqrtf(1.0f + 1e-5f);
    int total = COUT * CIN * 8;
    for (int idx = blockIdx.x * blockDim.x + threadIdx.x; idx < total;
         idx += gridDim.x * blockDim.x) {
        int k = idx & 7;
        int rest = idx >> 3;            // co*CIN + ci
        int co = rest / CIN;
        float sc = bng[co] * inv;
        float v = (k < 7) ? w[rest * 7 + k] * sc : 0.0f;
        wp[idx] = make_float2(v, v);
    }
    int t = blockIdx.x * blockDim.x + threadIdx.x;
    if (t < COUT) {
        float sc = bng[t] * inv;
        bbo[t] = cb[t] * sc + bnb[t];
    }
}

// ---------------- fused conv1d(k=7,pad=3)+BN+ReLU (+maxpool4), f32x2 --------
// 256 threads (8 warps). Block: batch b, 128 conv positions. Warp handles
// COUT/8 channels in quads; lane handles 4 consecutive positions as 2 f32x2 accs.
template<int CIN, int COUT, int POOL>
__global__ __launch_bounds__(256) void conv_f32x2(
    const float2* __restrict__ wp, const float* __restrict__ bb,
    const float* __restrict__ in, float* __restrict__ out,
    int Lin, int Lconv, int Lpool)
{
    constexpr int TLC = 128, RS = 136;
    extern __shared__ float s_in[];            // CIN * RS

    const int b = blockIdx.y;
    const int tile0 = blockIdx.x * TLC;
    const int tid = threadIdx.x;

    const float* inb = in + (size_t)b * CIN * Lin;
    for (int idx = tid; idx < CIN * (TLC + 6); idx += 256) {
        int ci = idx / (TLC + 6);
        int j = idx - ci * (TLC + 6);
        int p = tile0 - 3 + j;
        s_in[ci * RS + j] = (p >= 0 && p < Lin) ? inb[ci * Lin + p] : 0.0f;
    }
    __syncthreads();

    const int warp = tid >> 5, lane = tid & 31;
    const int l0 = lane * 4;
    constexpr int CPW = COUT / 8;
    constexpr int NQUAD = CPW / 4;

    #pragma unroll
    for (int q = 0; q < NQUAD; q++) {
        const int co0 = warp * CPW + q * 4;
        ull acc[4][2];
        #pragma unroll
        for (int c = 0; c < 4; c++) { acc[c][0] = 0ull; acc[c][1] = 0ull; }

        for (int ci = 0; ci < CIN; ci++) {
            const float* srow = s_in + ci * RS + l0;
            float4 xa = *(const float4*)(srow);
            float4 xb = *(const float4*)(srow + 4);
            float4 xc = *(const float4*)(srow + 8);
            ull px[9];
            px[0] = pack2(xa.x, xa.y); px[1] = pack2(xa.y, xa.z);
            px[2] = pack2(xa.z, xa.w); px[3] = pack2(xa.w, xb.x);
            px[4] = pack2(xb.x, xb.y); px[5] = pack2(xb.y, xb.z);
            px[6] = pack2(xb.z, xb.w); px[7] = pack2(xb.w, xc.x);
            px[8] = pack2(xc.x, xc.y);
            #pragma unroll
            for (int c = 0; c < 4; c++) {
                const ulonglong2* wr =
                    (const ulonglong2*)(wp + ((size_t)(co0 + c) * CIN + ci) * 8);
                ulonglong2 w01 = wr[0], w23 = wr[1], w45 = wr[2], w6x = wr[3];
                ull wk[7] = {w01.x, w01.y, w23.x, w23.y, w45.x, w45.y, w6x.x};
                #pragma unroll
                for (int k = 0; k < 7; k++) {
                    ffma2(acc[c][0], wk[k], px[k]);
                    ffma2(acc[c][1], wk[k], px[k + 2]);
                }
            }
        }
        #pragma unroll
        for (int c = 0; c < 4; c++) {
            const int co = co0 + c;
            const float bbv = bb[co];
            float y0, y1, y2, y3;
            unpack2(acc[c][0], y0, y1);
            unpack2(acc[c][1], y2, y3);
            y0 = fmaxf(y0 + bbv, 0.f); y1 = fmaxf(y1 + bbv, 0.f);
            y2 = fmaxf(y2 + bbv, 0.f); y3 = fmaxf(y3 + bbv, 0.f);
            if (POOL == 4) {
                int pi = (tile0 >> 2) + lane;
                if (pi < Lpool) {
                    float m = fmaxf(fmaxf(y0, y1), fmaxf(y2, y3));
                    out[((size_t)b * COUT + co) * Lpool + pi] = m;
                }
            } else {
                float ys[4] = {y0, y1, y2, y3};
                #pragma unroll
                for (int r = 0; r < 4; r++) {
                    int pos = tile0 + l0 + r;
                    if (pos < Lconv) out[((size_t)b * COUT + co) * Lconv + pos] = ys[r];
                }
            }
        }
    }
}

// ---------------- fused conv4 + BN + ReLU + mean -> feat (B,128) ------------
// grid (B, 4): block handles 32 output channels of batch b. 8 warps, 4 co each.
// Two 128-position sweeps cover L=187 (out-of-range lanes masked in epilogue).
__global__ __launch_bounds__(256) void conv4_mean(
    const float2* __restrict__ wp, const float* __restrict__ bb,
    const float* __restrict__ in, float* __restrict__ feat)
{
    constexpr int Lc = 187, RS = 200, CIN = 128;
    extern __shared__ float s_in[];            // CIN*RS + 128 pad

    const int b = blockIdx.x, tid = threadIdx.x;
    const float* inb = in + (size_t)b * CIN * Lc;
    for (int idx = tid; idx < CIN * 196; idx += 256) {
        int ci = idx / 196;
        int j = idx - ci * 196;
        int p = j - 3;
        s_in[ci * RS + j] = (p >= 0 && p < Lc) ? inb[ci * Lc + p] : 0.0f;
    }
    __syncthreads();

    const int warp = tid >> 5, lane = tid & 31;
    const int l0 = lane * 4;
    const int co0 = blockIdx.y * 32 + warp * 4;
    float sum[4] = {0.f, 0.f, 0.f, 0.f};

    #pragma unroll
    for (int sweep = 0; sweep < 2; sweep++) {
        const int tile0 = sweep * 128;
        ull acc[4][2];
        #pragma unroll
        for (int c = 0; c < 4; c++) { acc[c][0] = 0ull; acc[c][1] = 0ull; }

        for (int ci = 0; ci < CIN; ci++) {
            const float* srow = s_in + ci * RS + tile0 + l0;
            float4 xa = *(const float4*)(srow);
            float4 xb = *(const float4*)(srow + 4);
            float4 xc = *(const float4*)(srow + 8);
            ull px[9];
            px[0] = pack2(xa.x, xa.y); px[1] = pack2(xa.y, xa.z);
            px[2] = pack2(xa.z, xa.w); px[3] = pack2(xa.w, xb.x);
            px[4] = pack2(xb.x, xb.y); px[5] = pack2(xb.y, xb.z);
            px[6] = pack2(xb.z, xb.w); px[7] = pack2(xb.w, xc.x);
            px[8] = pack2(xc.x, xc.y);
            #pragma unroll
            for (int c = 0; c < 4; c++) {
                const ulonglong2* wr =
                    (const ulonglong2*)(wp + ((size_t)(co0 + c) * CIN + ci) * 8);
                ulonglong2 w01 = wr[0], w23 = wr[1], w45 = wr[2], w6x = wr[3];
                ull wk[7] = {w01.x, w01.y, w23.x, w23.y, w45.x, w45.y, w6x.x};
                #pragma unroll
                for (int k = 0; k < 7; k++) {
                    ffma2(acc[c][0], wk[k], px[k]);
                    ffma2(acc[c][1], wk[k], px[k + 2]);
                }
            }
        }
        #pragma unroll
        for (int c = 0; c < 4; c++) {
            const float bbv = bb[co0 + c];
            float y0, y1, y2, y3;
            unpack2(acc[c][0], y0, y1);
            unpack2(acc[c][1], y2, y3);
            int p = tile0 + l0;
            if (p     < Lc) sum[c] += fmaxf(y0 + bbv, 0.f);
            if (p + 1 < Lc) sum[c] += fmaxf(y1 + bbv, 0.f);
            if (p + 2 < Lc) sum[c] += fmaxf(y2 + bbv, 0.f);
            if (p + 3 < Lc) sum[c] += fmaxf(y3 + bbv, 0.f);
        }
    }
    #pragma unroll
    for (int c = 0; c < 4; c++) {
        float s = sum[c];
        #pragma unroll
        for (int o = 16; o; o >>= 1) s += __shfl_down_sync(0xffffffffu, s, o);
        if (lane == 0) feat[b * 128 + co0 + c] = s * (1.0f / 187.0f);
    }
}

// ---------------- fc(128->128)+relu, ang(128->8), angles = pi*tanh ----------
__global__ void head_kernel(const float* __restrict__ feat,
                            const float* __restrict__ fcw, const float* __restrict__ fcb,
                            const float* __restrict__ angw, const float* __restrict__ angb,
                            float* __restrict__ ang)
{
    int b = blockIdx.x, tid = threadIdx.x;  // 128 threads
    __shared__ float f[128];
    __shared__ float h[128];
    f[tid] = feat[b * 128 + tid];
    __syncthreads();
    float a = fcb[tid];
    const float* wr = fcw + tid * 128;
    #pragma unroll 8
    for (int k = 0; k < 128; k++) a = fmaf(wr[k], f[k], a);
    h[tid] = fmaxf(a, 0.f);
    __syncthreads();
    if (tid < NQ_) {
        float r = angb[tid];
        const float* ar = angw + tid * 128;
        #pragma unroll 8
        for (int k = 0; k < 128; k++) r = fmaf(ar[k], h[k], r);
        ang[b * NQ_ + tid] = 3.14159265358979323846f * tanhf(r);
    }
}

// ---------------- 8-qubit statevector sim + PauliZ + MLP head ----------------
__device__ __forceinline__ float2 cmul(float2 a, float2 b) {
    return make_float2(a.x * b.x - a.y * b.y, a.x * b.y + a.y * b.x);
}
__device__ __forceinline__ float2 cadd(float2 a, float2 b) {
    return make_float2(a.x + b.x, a.y + b.y);
}

__global__ void qsim_kernel(const float* __restrict__ ang, const float* __restrict__ qw,
                            const float* __restrict__ h1w, const float* __restrict__ h1b,
                            const float* __restrict__ h2w, const float* __restrict__ h2b,
                            float* __restrict__ out)
{
    int b = blockIdx.x, i = threadIdx.x;  // 256 threads, one amplitude each
    __shared__ float2 st[256];
    st[i] = make_float2(i == 0 ? 1.f : 0.f, 0.f);
    __syncthreads();

    for (int wq = 0; wq < NQ_; wq++) {
        int m = 1 << (7 - wq);
        float a = 0.5f * ang[b * NQ_ + wq];
        float c = cosf(a), s = sinf(a);
        if ((i & m) == 0) {
            float2 a0 = st[i], a1 = st[i | m];
            st[i]     = make_float2(c * a0.x - s * a1.x, c * a0.y - s * a1.y);
            st[i | m] = make_float2(s * a0.x + c * a1.x, s * a0.y + c * a1.y);
        }
        __syncthreads();
    }

    for (int l = 0; l < NL_; l++) {
        for (int wq = 0; wq < NQ_; wq++) {
            int m = 1 << (7 - wq);
            const float* p = qw + (l * NQ_ + wq) * 3;
            float phi = p[0], th = p[1], om = p[2];
            float cm = cosf(0.5f * th), sm = sinf(0.5f * th);
            float hpo = 0.5f * (phi + om), hpm = 0.5f * (phi - om);
            float2 m00 = make_float2( cm * cosf(hpo), -cm * sinf(hpo));
            float2 m01 = make_float2(-sm * cosf(hpm), -sm * sinf(hpm));
            float2 m10 = make_float2( sm * cosf(hpm), -sm * sinf(hpm));
            float2 m11 = make_float2( cm * cosf(hpo),  cm * sinf(hpo));
            if ((i & m) == 0) {
                float2 a0 = st[i], a1 = st[i | m];
                st[i]     = cadd(cmul(m00, a0), cmul(m01, a1));
                st[i | m] = cadd(cmul(m10, a0), cmul(m11, a1));
            }
            __syncthreads();
        }
        int r = (l % (NQ_ - 1)) + 1;
        for (int q = 0; q < NQ_; q++) {
            int c = q, t = (q + r) & 7;
            int mc = 1 << (7 - c), mt = 1 << (7 - t);
            if ((i & mc) && !(i & mt)) {
                float2 tmp = st[i];
                st[i] = st[i | mt];
                st[i | mt] = tmp;
            }
            __syncthreads();
        }
    }

    __shared__ float pr[256];
    pr[i] = st[i].x * st[i].x + st[i].y * st[i].y;
    __syncthreads();

    __shared__ float z[NQ_];
    if (i < NQ_) {
        float s = 0.f;
        int sh = 7 - i;
        for (int j = 0; j < 256; j++) s += ((j >> sh) & 1) ? -pr[j] : pr[j];
        z[i] = s;
    }
    __syncthreads();

    __shared__ float h1[64];
    if (i < 64) {
        float a = h1b[i];
        #pragma unroll
        for (int k = 0; k < NQ_; k++) a = fmaf(h1w[i * NQ_ + k], z[k], a);
        h1[i] = fmaxf(a, 0.f);
    }
    __syncthreads();

    if (i < NCLS_) {
        float a = h2b[i];
        #pragma unroll 8
        for (int k = 0; k < 64; k++) a = fmaf(h2w[i * 64 + k], h1[k], a);
        out[b * NCLS_ + i] = a;
    }
}

// ---------------- launch ----------------
extern "C" void kernel_launch(void* const* d_in, const int* in_sizes, int n_in,
                              void* d_out, int out_size)
{
    const float* x       = (const float*)d_in[0];
    const float* conv1_w = (const float*)d_in[1];
    const float* conv1_b = (const float*)d_in[2];
    const float* bn1_g   = (const float*)d_in[3];
    const float* bn1_b   = (const float*)d_in[4];
    const float* conv2_w = (const float*)d_in[5];
    const float* conv2_b = (const float*)d_in[6];
    const float* bn2_g   = (const float*)d_in[7];
    const float* bn2_b   = (const float*)d_in[8];
    const float* conv3_w = (const float*)d_in[9];
    const float* conv3_b = (const float*)d_in[10];
    const float* bn3_g   = (const float*)d_in[11];
    const float* bn3_b   = (const float*)d_in[12];
    const float* conv4_w = (const float*)d_in[13];
    const float* conv4_b = (const float*)d_in[14];
    const float* bn4_g   = (const float*)d_in[15];
    const float* bn4_b   = (const float*)d_in[16];
    const float* fc_w    = (const float*)d_in[17];
    const float* fc_b    = (const float*)d_in[18];
    const float* ang_w   = (const float*)d_in[19];
    const float* ang_b   = (const float*)d_in[20];
    const float* qw      = (const float*)d_in[21];
    const float* h1_w    = (const float*)d_in[22];
    const float* h1_b    = (const float*)d_in[23];
    const float* h2_w    = (const float*)d_in[24];
    const float* h2_b    = (const float*)d_in[25];
    float* out = (float*)d_out;

    float *b1, *b2, *b3, *feat, *ang;
    float2 *wp1, *wp2, *wp3, *wp4;
    float *bb1, *bb2, *bb3, *bb4;
    cudaGetSymbolAddress((void**)&b1, g_buf1);
    cudaGetSymbolAddress((void**)&b2, g_buf2);
    cudaGetSymbolAddress((void**)&b3, g_buf3);
    cudaGetSymbolAddress((void**)&feat, g_feat);
    cudaGetSymbolAddress((void**)&ang, g_ang);
    cudaGetSymbolAddress((void**)&wp1, g_wp1);
    cudaGetSymbolAddress((void**)&wp2, g_wp2);
    cudaGetSymbolAddress((void**)&wp3, g_wp3);
    cudaGetSymbolAddress((void**)&wp4, g_wp4);
    cudaGetSymbolAddress((void**)&bb1, g_bb1);
    cudaGetSymbolAddress((void**)&bb2, g_bb2);
    cudaGetSymbolAddress((void**)&bb3, g_bb3);
    cudaGetSymbolAddress((void**)&bb4, g_bb4);

    // weight prepack (fold BN, duplicate pairs, pad k to 8)
    prep_kernel<<<(32 * 4 * 8 + 255) / 256, 256>>>(conv1_w, conv1_b, bn1_g, bn1_b, wp1, bb1, 4, 32);
    prep_kernel<<<(64 * 32 * 8 + 255) / 256, 256>>>(conv2_w, conv2_b, bn2_g, bn2_b, wp2, bb2, 32, 64);
    prep_kernel<<<(128 * 64 * 8 + 255) / 256, 256>>>(conv3_w, conv3_b, bn3_g, bn3_b, wp3, bb3, 64, 128);
    prep_kernel<<<(128 * 128 * 8 + 255) / 256, 256>>>(conv4_w, conv4_b, bn4_g, bn4_b, wp4, bb4, 128, 128);

    constexpr int RS = 136;
    size_t sm1 = (size_t)4  * RS * 4;
    size_t sm2 = (size_t)32 * RS * 4;
    size_t sm3 = (size_t)64 * RS * 4;
    size_t sm4 = (size_t)(128 * 200 + 128) * 4;   // 102912

    cudaFuncSetAttribute(conv4_mean, cudaFuncAttributeMaxDynamicSharedMemorySize, (int)sm4);

    // conv1: (B,4,3000) -> (B,32,3000)
    conv_f32x2<4, 32, 1><<<dim3(24, B_), 256, sm1>>>(wp1, bb1, x, b1, 3000, 3000, 0);
    // conv2 + pool4: -> (B,64,750)
    conv_f32x2<32, 64, 4><<<dim3(24, B_), 256, sm2>>>(wp2, bb2, b1, b2, 3000, 3000, 750);
    // conv3 + pool4: -> (B,128,187)
    conv_f32x2<64, 128, 4><<<dim3(6, B_), 256, sm3>>>(wp3, bb3, b2, b3, 750, 750, 187);
    // conv4 + mean: -> (B,128)
    conv4_mean<<<dim3(B_, 4), 256, sm4>>>(wp4, bb4, b3, feat);
    // fc + ang head -> angles (B,8)
    head_kernel<<<B_, 128>>>(feat, fc_w, fc_b, ang_w, ang_b, ang);
    // quantum sim + final MLP -> (B,5)
    qsim_kernel<<<B_, 256>>>(ang, qw, h1_w, h1_b, h2_w, h2_b, out);
}

// round 3
// speedup vs baseline: 1.8744x; 1.5595x over previous
#include <cuda_runtime.h>
#include <cuda_bf16.h>
#include <math.h>

#define B_ 256
#define NQ_ 8
#define NL_ 2
#define NCLS_ 5

typedef unsigned long long ull;

// ---------------- scratch buffers ----------------
__device__ float g_buf1[B_ * 32 * 3000];   // conv1 out
__device__ float g_buf2[B_ * 64 * 750];    // conv2+pool out
__device__ float g_buf3[B_ * 128 * 187];   // conv3+pool out
__device__ float g_feat[B_ * 128];         // conv4+mean out
__device__ float g_ang[B_ * NQ_];          // angles

// prepacked weights: [(co*CIN+ci)*8 + k] as float2(w*sc, w*sc), k=7 zero-padded
__device__ float2 g_wp1[32 * 4 * 8];
__device__ float2 g_wp2[64 * 32 * 8];
__device__ float2 g_wp3[128 * 64 * 8];
__device__ float2 g_wp4[128 * 128 * 8];
__device__ float  g_bb1[32], g_bb2[64], g_bb3[128], g_bb4[128];

// ---------------- f32x2 helpers ----------------
__device__ __forceinline__ ull pack2(float lo, float hi) {
    ull r; asm("mov.b64 %0,{%1,%2};" : "=l"(r) : "f"(lo), "f"(hi)); return r;
}
__device__ __forceinline__ void unpack2(ull v, float& lo, float& hi) {
    asm("mov.b64 {%0,%1},%2;" : "=f"(lo), "=f"(hi) : "l"(v));
}
__device__ __forceinline__ void ffma2(ull& acc, ull a, ull b) {
    asm("fma.rn.f32x2 %0,%1,%2,%0;" : "+l"(acc) : "l"(a), "l"(b));
}

// ---------------- single merged prepack for all 4 conv layers ----------------
__device__ void prep_one(const float* w, const float* cb, const float* bng,
                         const float* bnb, float2* wp, float* bbo,
                         int CIN, int COUT, int idx)
{
    const float inv = rsqrtf(1.0f + 1e-5f);
    int total = COUT * CIN * 8;
    if (idx < total) {
        int k = idx & 7;
        int rest = idx >> 3;
        int co = rest / CIN;
        float sc = bng[co] * inv;
        float v = (k < 7) ? w[rest * 7 + k] * sc : 0.0f;
        wp[idx] = make_float2(v, v);
    }
    if (idx < COUT) {
        float sc = bng[idx] * inv;
        bbo[idx] = cb[idx] * sc + bnb[idx];
    }
}

__global__ void prep_all(
    const float* w1, const float* b1, const float* g1, const float* be1,
    const float* w2, const float* b2, const float* g2, const float* be2,
    const float* w3, const float* b3, const float* g3, const float* be3,
    const float* w4, const float* b4, const float* g4, const float* be4,
    float2* wp1, float* bb1, float2* wp2, float* bb2,
    float2* wp3, float* bb3, float2* wp4, float* bb4)
{
    const int T1 = 32 * 4 * 8, T2 = 64 * 32 * 8, T3 = 128 * 64 * 8, T4 = 128 * 128 * 8;
    int idx = blockIdx.x * blockDim.x + threadIdx.x;
    if (idx < T1)                prep_one(w1, b1, g1, be1, wp1, bb1, 4, 32, idx);
    if (idx < T2)                prep_one(w2, b2, g2, be2, wp2, bb2, 32, 64, idx);
    if (idx < T3)                prep_one(w3, b3, g3, be3, wp3, bb3, 64, 128, idx);
    if (idx < T4)                prep_one(w4, b4, g4, be4, wp4, bb4, 128, 128, idx);
}

// ---------------- fused conv1d(k=7,pad=3)+BN+ReLU (+maxpool4), f32x2 --------
// 256 threads (8 warps). Lane covers 8 consecutive positions (4 f32x2 accs).
// Tile = 256 positions. Warp handles COUT/8 channels in quads of 4.
template<int CIN, int COUT, int POOL>
__global__ __launch_bounds__(256, 2) void conv_f32x2(
    const float2* __restrict__ wp, const float* __restrict__ bb,
    const float* __restrict__ in, float* __restrict__ out,
    int Lin, int Lconv, int Lpool)
{
    constexpr int PPL = 8;              // positions per lane
    constexpr int TLP = 256;            // positions per tile
    constexpr int RS  = TLP + 16;       // smem row stride
    extern __shared__ float s_in[];     // CIN * RS

    const int b = blockIdx.y;
    const int tile0 = blockIdx.x * TLP;
    const int tid = threadIdx.x;
    const int warp = tid >> 5, lane = tid & 31;

    const float* inb = in + (size_t)b * CIN * Lin;
    for (int ci = warp; ci < CIN; ci += 8)
        for (int j = lane; j < RS; j += 32) {
            int p = tile0 - 3 + j;
            s_in[ci * RS + j] = (p >= 0 && p < Lin) ? inb[ci * Lin + p] : 0.0f;
        }
    __syncthreads();

    const int l0 = lane * PPL;
    constexpr int CPW = COUT / 8;
    constexpr int NQUAD = CPW / 4;

    #pragma unroll
    for (int q = 0; q < NQUAD; q++) {
        const int co0 = warp * CPW + q * 4;
        ull acc[4][4] = {};

        for (int ci = 0; ci < CIN; ci++) {
            const float* srow = s_in + ci * RS + l0;
            float4 v0 = *(const float4*)(srow);
            float4 v1 = *(const float4*)(srow + 4);
            float4 v2 = *(const float4*)(srow + 8);
            float4 v3 = *(const float4*)(srow + 12);
            float v[16] = {v0.x, v0.y, v0.z, v0.w, v1.x, v1.y, v1.z, v1.w,
                           v2.x, v2.y, v2.z, v2.w, v3.x, v3.y, v3.z, v3.w};
            ull px[13];
            #pragma unroll
            for (int j = 0; j < 13; j++) px[j] = pack2(v[j], v[j + 1]);
            #pragma unroll
            for (int c = 0; c < 4; c++) {
                const ulonglong2* wr =
                    (const ulonglong2*)(wp + ((size_t)(co0 + c) * CIN + ci) * 8);
                ulonglong2 w01 = wr[0], w23 = wr[1], w45 = wr[2], w6x = wr[3];
                ull wk[7] = {w01.x, w01.y, w23.x, w23.y, w45.x, w45.y, w6x.x};
                #pragma unroll
                for (int k = 0; k < 7; k++) {
                    ffma2(acc[c][0], wk[k], px[k]);
                    ffma2(acc[c][1], wk[k], px[k + 2]);
                    ffma2(acc[c][2], wk[k], px[k + 4]);
                    ffma2(acc[c][3], wk[k], px[k + 6]);
                }
            }
        }
        #pragma unroll
        for (int c = 0; c < 4; c++) {
            const int co = co0 + c;
            const float bbv = bb[co];
            float y[8];
            #pragma unroll
            for (int a = 0; a < 4; a++) {
                unpack2(acc[c][a], y[2 * a], y[2 * a + 1]);
                y[2 * a]     = fmaxf(y[2 * a] + bbv, 0.f);
                y[2 * a + 1] = fmaxf(y[2 * a + 1] + bbv, 0.f);
            }
            if (POOL == 4) {
                float m0 = fmaxf(fmaxf(y[0], y[1]), fmaxf(y[2], y[3]));
                float m1 = fmaxf(fmaxf(y[4], y[5]), fmaxf(y[6], y[7]));
                int pi = (tile0 >> 2) + lane * 2;
                float* op = out + ((size_t)b * COUT + co) * Lpool;
                if (pi < Lpool)     op[pi] = m0;
                if (pi + 1 < Lpool) op[pi + 1] = m1;
            } else {
                int pos = tile0 + l0;
                float* op = out + ((size_t)b * COUT + co) * Lconv + pos;
                if (pos + 7 < Lconv) {
                    *(float4*)(op)     = make_float4(y[0], y[1], y[2], y[3]);
                    *(float4*)(op + 4) = make_float4(y[4], y[5], y[6], y[7]);
                } else {
                    #pragma unroll
                    for (int r = 0; r < 8; r++)
                        if (pos + r < Lconv) op[r] = y[r];
                }
            }
        }
    }
}

// ---------------- fused conv4 + BN + ReLU + mean -> feat (B,128) ------------
// grid (4, B): block = 32 output channels of batch b; warp -> 4 co.
// Single sweep: lane covers 6 positions (3 f32x2 accs), 192 >= 187.
__global__ __launch_bounds__(256, 2) void conv4_mean(
    const float2* __restrict__ wp, const float* __restrict__ bb,
    const float* __restrict__ in, float* __restrict__ feat)
{
    constexpr int CIN = 128, Lc = 187, RS = 208;
    extern __shared__ float s_in[];    // 128 * 208

    const int b = blockIdx.y, tid = threadIdx.x;
    const int warp = tid >> 5, lane = tid & 31;

    const float* inb = in + (size_t)b * CIN * Lc;
    for (int ci = warp; ci < CIN; ci += 8)
        for (int j = lane; j < RS; j += 32) {
            int p = j - 3;
            s_in[ci * RS + j] = (p >= 0 && p < Lc) ? inb[ci * Lc + p] : 0.0f;
        }
    __syncthreads();

    const int l0 = lane * 6;
    const int co0 = blockIdx.x * 32 + warp * 4;
    ull acc[4][3] = {};

    for (int ci = 0; ci < CIN; ci++) {
        const float* srow = s_in + ci * RS + l0;
        float4 v0 = *(const float4*)(srow);      // l0 multiple of... 6*lane, not 16B aligned!
        // NOTE: l0*4 bytes = lane*24 bytes -> not 16B aligned for odd lanes.
        // Use two float2-ish scalar-safe loads instead:
        (void)v0;
        float v[12];
        #pragma unroll
        for (int t = 0; t < 6; t++) {
            float2 vv = *(const float2*)(srow + 2 * t);   // 8B aligned: l0 even ✓
            v[2 * t] = vv.x; v[2 * t + 1] = vv.y;
        }
        ull px[11];
        #pragma unroll
        for (int j = 0; j < 11; j++) px[j] = pack2(v[j], v[j + 1]);
        #pragma unroll
        for (int c = 0; c < 4; c++) {
            const ulonglong2* wr =
                (const ulonglong2*)(wp + ((size_t)(co0 + c) * CIN + ci) * 8);
            ulonglong2 w01 = wr[0], w23 = wr[1], w45 = wr[2], w6x = wr[3];
            ull wk[7] = {w01.x, w01.y, w23.x, w23.y, w45.x, w45.y, w6x.x};
            #pragma unroll
            for (int k = 0; k < 7; k++) {
                ffma2(acc[c][0], wk[k], px[k]);
                ffma2(acc[c][1], wk[k], px[k + 2]);
                ffma2(acc[c][2], wk[k], px[k + 4]);
            }
        }
    }

    #pragma unroll
    for (int c = 0; c < 4; c++) {
        const float bbv = bb[co0 + c];
        float s = 0.f;
        #pragma unroll
        for (int a = 0; a < 3; a++) {
            float ylo, yhi;
            unpack2(acc[c][a], ylo, yhi);
            int p = l0 + 2 * a;
            if (p < Lc)     s += fmaxf(ylo + bbv, 0.f);
            if (p + 1 < Lc) s += fmaxf(yhi + bbv, 0.f);
        }
        #pragma unroll
        for (int o = 16; o; o >>= 1) s += __shfl_down_sync(0xffffffffu, s, o);
        if (lane == 0) feat[b * 128 + co0 + c] = s * (1.0f / 187.0f);
    }
}

// ---------------- fc(128->128)+relu, ang(128->8), angles = pi*tanh ----------
__global__ void head_kernel(const float* __restrict__ feat,
                            const float* __restrict__ fcw, const float* __restrict__ fcb,
                            const float* __restrict__ angw, const float* __restrict__ angb,
                            float* __restrict__ ang)
{
    int b = blockIdx.x, tid = threadIdx.x;  // 128 threads
    __shared__ float f[128];
    __shared__ float h[128];
    f[tid] = feat[b * 128 + tid];
    __syncthreads();
    float a = fcb[tid];
    const float* wr = fcw + tid * 128;
    #pragma unroll 8
    for (int k = 0; k < 128; k++) a = fmaf(wr[k], f[k], a);
    h[tid] = fmaxf(a, 0.f);
    __syncthreads();
    if (tid < NQ_) {
        float r = angb[tid];
        const float* ar = angw + tid * 128;
        #pragma unroll 8
        for (int k = 0; k < 128; k++) r = fmaf(ar[k], h[k], r);
        ang[b * NQ_ + tid] = 3.14159265358979323846f * tanhf(r);
    }
}

// ---------------- 8-qubit statevector sim + PauliZ + MLP head ----------------
__device__ __forceinline__ float2 cmul(float2 a, float2 b) {
    return make_float2(a.x * b.x - a.y * b.y, a.x * b.y + a.y * b.x);
}
__device__ __forceinline__ float2 cadd(float2 a, float2 b) {
    return make_float2(a.x + b.x, a.y + b.y);
}

__global__ void qsim_kernel(const float* __restrict__ ang, const float* __restrict__ qw,
                            const float* __restrict__ h1w, const float* __restrict__ h1b,
                            const float* __restrict__ h2w, const float* __restrict__ h2b,
                            float* __restrict__ out)
{
    int b = blockIdx.x, i = threadIdx.x;  // 256 threads, one amplitude each
    __shared__ float2 st[256];
    st[i] = make_float2(i == 0 ? 1.f : 0.f, 0.f);
    __syncthreads();

    for (int wq = 0; wq < NQ_; wq++) {
        int m = 1 << (7 - wq);
        float a = 0.5f * ang[b * NQ_ + wq];
        float c = cosf(a), s = sinf(a);
        if ((i & m) == 0) {
            float2 a0 = st[i], a1 = st[i | m];
            st[i]     = make_float2(c * a0.x - s * a1.x, c * a0.y - s * a1.y);
            st[i | m] = make_float2(s * a0.x + c * a1.x, s * a0.y + c * a1.y);
        }
        __syncthreads();
    }

    for (int l = 0; l < NL_; l++) {
        for (int wq = 0; wq < NQ_; wq++) {
            int m = 1 << (7 - wq);
            const float* p = qw + (l * NQ_ + wq) * 3;
            float phi = p[0], th = p[1], om = p[2];
            float cm = cosf(0.5f * th), sm = sinf(0.5f * th);
            float hpo = 0.5f * (phi + om), hpm = 0.5f * (phi - om);
            float2 m00 = make_float2( cm * cosf(hpo), -cm * sinf(hpo));
            float2 m01 = make_float2(-sm * cosf(hpm), -sm * sinf(hpm));
            float2 m10 = make_float2( sm * cosf(hpm), -sm * sinf(hpm));
            float2 m11 = make_float2( cm * cosf(hpo),  cm * sinf(hpo));
            if ((i & m) == 0) {
                float2 a0 = st[i], a1 = st[i | m];
                st[i]     = cadd(cmul(m00, a0), cmul(m01, a1));
                st[i | m] = cadd(cmul(m10, a0), cmul(m11, a1));
            }
            __syncthreads();
        }
        int r = (l % (NQ_ - 1)) + 1;
        for (int q = 0; q < NQ_; q++) {
            int c = q, t = (q + r) & 7;
            int mc = 1 << (7 - c), mt = 1 << (7 - t);
            if ((i & mc) && !(i & mt)) {
                float2 tmp = st[i];
                st[i] = st[i | mt];
                st[i | mt] = tmp;
            }
            __syncthreads();
        }
    }

    __shared__ float pr[256];
    pr[i] = st[i].x * st[i].x + st[i].y * st[i].y;
    __syncthreads();

    __shared__ float z[NQ_];
    if (i < NQ_) {
        float s = 0.f;
        int sh = 7 - i;
        for (int j = 0; j < 256; j++) s += ((j >> sh) & 1) ? -pr[j] : pr[j];
        z[i] = s;
    }
    __syncthreads();

    __shared__ float h1[64];
    if (i < 64) {
        float a = h1b[i];
        #pragma unroll
        for (int k = 0; k < NQ_; k++) a = fmaf(h1w[i * NQ_ + k], z[k], a);
        h1[i] = fmaxf(a, 0.f);
    }
    __syncthreads();

    if (i < NCLS_) {
        float a = h2b[i];
        #pragma unroll 8
        for (int k = 0; k < 64; k++) a = fmaf(h2w[i * 64 + k], h1[k], a);
        out[b * NCLS_ + i] = a;
    }
}

// ---------------- launch ----------------
extern "C" void kernel_launch(void* const* d_in, const int* in_sizes, int n_in,
                              void* d_out, int out_size)
{
    const float* x       = (const float*)d_in[0];
    const float* conv1_w = (const float*)d_in[1];
    const float* conv1_b = (const float*)d_in[2];
    const float* bn1_g   = (const float*)d_in[3];
    const float* bn1_b   = (const float*)d_in[4];
    const float* conv2_w = (const float*)d_in[5];
    const float* conv2_b = (const float*)d_in[6];
    const float* bn2_g   = (const float*)d_in[7];
    const float* bn2_b   = (const float*)d_in[8];
    const float* conv3_w = (const float*)d_in[9];
    const float* conv3_b = (const float*)d_in[10];
    const float* bn3_g   = (const float*)d_in[11];
    const float* bn3_b   = (const float*)d_in[12];
    const float* conv4_w = (const float*)d_in[13];
    const float* conv4_b = (const float*)d_in[14];
    const float* bn4_g   = (const float*)d_in[15];
    const float* bn4_b   = (const float*)d_in[16];
    const float* fc_w    = (const float*)d_in[17];
    const float* fc_b    = (const float*)d_in[18];
    const float* ang_w   = (const float*)d_in[19];
    const float* ang_b   = (const float*)d_in[20];
    const float* qw      = (const float*)d_in[21];
    const float* h1_w    = (const float*)d_in[22];
    const float* h1_b    = (const float*)d_in[23];
    const float* h2_w    = (const float*)d_in[24];
    const float* h2_b    = (const float*)d_in[25];
    float* out = (float*)d_out;

    float *b1, *b2, *b3, *feat, *ang;
    float2 *wp1, *wp2, *wp3, *wp4;
    float *bb1, *bb2, *bb3, *bb4;
    cudaGetSymbolAddress((void**)&b1, g_buf1);
    cudaGetSymbolAddress((void**)&b2, g_buf2);
    cudaGetSymbolAddress((void**)&b3, g_buf3);
    cudaGetSymbolAddress((void**)&feat, g_feat);
    cudaGetSymbolAddress((void**)&ang, g_ang);
    cudaGetSymbolAddress((void**)&wp1, g_wp1);
    cudaGetSymbolAddress((void**)&wp2, g_wp2);
    cudaGetSymbolAddress((void**)&wp3, g_wp3);
    cudaGetSymbolAddress((void**)&wp4, g_wp4);
    cudaGetSymbolAddress((void**)&bb1, g_bb1);
    cudaGetSymbolAddress((void**)&bb2, g_bb2);
    cudaGetSymbolAddress((void**)&bb3, g_bb3);
    cudaGetSymbolAddress((void**)&bb4, g_bb4);

    // merged weight prepack
    prep_all<<<(128 * 128 * 8 + 255) / 256, 256>>>(
        conv1_w, conv1_b, bn1_g, bn1_b, conv2_w, conv2_b, bn2_g, bn2_b,
        conv3_w, conv3_b, bn3_g, bn3_b, conv4_w, conv4_b, bn4_g, bn4_b,
        wp1, bb1, wp2, bb2, wp3, bb3, wp4, bb4);

    constexpr int RS = 272;
    size_t sm1 = (size_t)4  * RS * 4;
    size_t sm2 = (size_t)32 * RS * 4;
    size_t sm3 = (size_t)64 * RS * 4;     // 69632
    size_t sm4 = (size_t)128 * 208 * 4;   // 106496

    cudaFuncSetAttribute(conv_f32x2<64, 128, 4>,
                         cudaFuncAttributeMaxDynamicSharedMemorySize, (int)sm3);
    cudaFuncSetAttribute(conv4_mean,
                         cudaFuncAttributeMaxDynamicSharedMemorySize, (int)sm4);

    // conv1: (B,4,3000) -> (B,32,3000)
    conv_f32x2<4, 32, 1><<<dim3(12, B_), 256, sm1>>>(wp1, bb1, x, b1, 3000, 3000, 0);
    // conv2 + pool4: -> (B,64,750)
    conv_f32x2<32, 64, 4><<<dim3(12, B_), 256, sm2>>>(wp2, bb2, b1, b2, 3000, 3000, 750);
    // conv3 + pool4: -> (B,128,187)
    conv_f32x2<64, 128, 4><<<dim3(3, B_), 256, sm3>>>(wp3, bb3, b2, b3, 750, 750, 187);
    // conv4 + mean: -> (B,128)
    conv4_mean<<<dim3(4, B_), 256, sm4>>>(wp4, bb4, b3, feat);
    // fc + ang head -> angles (B,8)
    head_kernel<<<B_, 128>>>(feat, fc_w, fc_b, ang_w, ang_b, ang);
    // quantum sim + final MLP -> (B,5)
    qsim_kernel<<<B_, 256>>>(ang, qw, h1_w, h1_b, h2_w, h2_b, out);
}

// round 4
// speedup vs baseline: 5.5124x; 2.9409x over previous
#include <cuda_runtime.h>
#include <cuda_bf16.h>
#include <math.h>

#define B_ 256
#define NQ_ 8
#define NL_ 2
#define NCLS_ 5

// ---------------- scratch buffers ----------------
__device__ float g_buf1[B_ * 32 * 3000];   // conv1 out
__device__ float g_buf2[B_ * 64 * 750];    // conv2+pool out
__device__ float g_buf3[B_ * 128 * 187];   // conv3+pool out
__device__ float g_feat[B_ * 128];         // conv4 sums (atomic)
__device__ float g_ang[B_ * NQ_];          // angles

// fragment-ordered tf32 weights: [(mt*KSTEPS+ks)*32+lane] -> uint4 (a0..a3)
__device__ uint4 g_ap1[2 * 4 * 32];        // COUT/16 * CIN * 32
__device__ uint4 g_ap2[4 * 32 * 32];
__device__ uint4 g_ap3[8 * 64 * 32];
__device__ uint4 g_ap4[8 * 128 * 32];
__device__ float g_bb1[32], g_bb2[64], g_bb3[128], g_bb4[128];

// ---------------- prepack: BN-fold, tf32-round, fragment order ----------------
__device__ __forceinline__ unsigned tf32_rna(float v) {
    unsigned r; asm("cvt.rna.tf32.f32 %0,%1;" : "=r"(r) : "f"(v)); return r;
}

__device__ void prep_one(const float* w, const float* cb, const float* bng,
                         const float* bnb, unsigned* ap, float* bbo,
                         int CIN, int COUT, int idx)
{
    const float inv = rsqrtf(1.0f + 1e-5f);
    int total = COUT * CIN * 8;
    if (idx < total) {
        int i = idx & 3;
        int lane = (idx >> 2) & 31;
        int t = idx >> 7;
        int ks = t % CIN;
        int mt = t / CIN;
        int co = mt * 16 + (lane >> 2) + ((i & 1) ? 8 : 0);
        int k  = (lane & 3) + ((i & 2) ? 4 : 0);
        float v = (k < 7) ? w[(co * CIN + ks) * 7 + k] * (bng[co] * inv) : 0.0f;
        ap[idx] = tf32_rna(v);
    }
    if (idx < COUT) {
        float sc = bng[idx] * inv;
        bbo[idx] = cb[idx] * sc + bnb[idx];
    }
}

__global__ void prep_all(
    const float* w1, const float* b1, const float* g1, const float* be1,
    const float* w2, const float* b2, const float* g2, const float* be2,
    const float* w3, const float* b3, const float* g3, const float* be3,
    const float* w4, const float* b4, const float* g4, const float* be4,
    unsigned* ap1, float* bb1, unsigned* ap2, float* bb2,
    unsigned* ap3, float* bb3, unsigned* ap4, float* bb4, float* feat)
{
    int idx = blockIdx.x * blockDim.x + threadIdx.x;
    prep_one(w1, b1, g1, be1, ap1, bb1, 4, 32, idx);
    prep_one(w2, b2, g2, be2, ap2, bb2, 32, 64, idx);
    prep_one(w3, b3, g3, be3, ap3, bb3, 64, 128, idx);
    prep_one(w4, b4, g4, be4, ap4, bb4, 128, 128, idx);
    if (idx < B_ * 128) feat[idx] = 0.0f;
}

// ---------------- tf32 mma helper ----------------
__device__ __forceinline__ void mma_tf32(float* d, const uint4& a,
                                         unsigned b0, unsigned b1)
{
    asm volatile(
        "mma.sync.aligned.m16n8k8.row.col.f32.tf32.tf32.f32 "
        "{%0,%1,%2,%3},{%4,%5,%6,%7},{%8,%9},{%0,%1,%2,%3};"
        : "+f"(d[0]), "+f"(d[1]), "+f"(d[2]), "+f"(d[3])
        : "r"(a.x), "r"(a.y), "r"(a.z), "r"(a.w), "r"(b0), "r"(b1));
}

// ---------------- conv1d(k=7,pad=3)+BN+ReLU(+maxpool4) as implicit GEMM ------
// MODE: 0 = plain store, 4 = maxpool4 store.
// Block: 256 threads, one batch b, 128 conv positions. WM = COUT/16 warps on M,
// WN = 8/WM warp-groups on N. NSW n-steps (of 8 positions) per warp.
template<int CIN, int COUT, int MODE>
__global__ __launch_bounds__(256) void conv_mma(
    const uint4* __restrict__ Ap, const float* __restrict__ bb,
    const float* __restrict__ in, float* __restrict__ out,
    int Lin, int Lconv, int Lpool)
{
    constexpr int WM = COUT / 16;
    constexpr int WN = 8 / WM;
    constexpr int NSW = 16 / WN;        // n-steps per warp
    constexpr int KSTEPS = CIN;
    constexpr int RS = 144;             // smem row stride (floats)
    constexpr int JW = 136;             // loaded width (halo 3 + 128 + 5)
    extern __shared__ float s_in[];     // CIN * RS

    const int b = blockIdx.y;
    const int tile0 = blockIdx.x * 128;
    const int tid = threadIdx.x;

    const float* inb = in + (size_t)b * CIN * Lin;
    for (int idx = tid; idx < CIN * JW; idx += 256) {
        int ci = idx / JW;
        int j = idx - ci * JW;
        int p = tile0 - 3 + j;
        s_in[ci * RS + j] = (p >= 0 && p < Lin) ? inb[ci * Lin + p] : 0.0f;
    }
    __syncthreads();

    const int wid = tid >> 5, lane = tid & 31;
    const int mt = wid % WM;
    const int ng_off = (wid / WM) * (NSW * 8);
    const unsigned* sp = (const unsigned*)s_in;

    float acc[NSW][4] = {};
    const int boff = ng_off + (lane >> 2) + (lane & 3);

    for (int ks = 0; ks < KSTEPS; ks++) {
        uint4 a = Ap[(mt * KSTEPS + ks) * 32 + lane];
        const unsigned* srow = sp + ks * RS + boff;
        #pragma unroll
        for (int ns = 0; ns < NSW; ns++) {
            unsigned b0 = srow[ns * 8];
            unsigned b1 = srow[ns * 8 + 4];
            mma_tf32(acc[ns], a, b0, b1);
        }
    }

    // epilogue
    const int row0 = lane >> 2;
    const int co0 = mt * 16 + row0;
    const int co1 = co0 + 8;
    const float bv0 = bb[co0], bv1 = bb[co1];

    #pragma unroll
    for (int ns = 0; ns < NSW; ns++) {
        int pos = tile0 + ng_off + ns * 8 + 2 * (lane & 3);
        if (MODE == 0) {
            if (pos < Lconv) {
                float y0 = fmaxf(acc[ns][0] + bv0, 0.f);
                float y1 = fmaxf(acc[ns][1] + bv0, 0.f);
                float y2 = fmaxf(acc[ns][2] + bv1, 0.f);
                float y3 = fmaxf(acc[ns][3] + bv1, 0.f);
                *(float2*)(out + ((size_t)b * COUT + co0) * Lconv + pos) = make_float2(y0, y1);
                *(float2*)(out + ((size_t)b * COUT + co1) * Lconv + pos) = make_float2(y2, y3);
            }
        } else {
            float m0 = fmaxf(fmaxf(acc[ns][0], acc[ns][1]) + bv0, 0.f);
            float m1 = fmaxf(fmaxf(acc[ns][2], acc[ns][3]) + bv1, 0.f);
            m0 = fmaxf(m0, __shfl_xor_sync(0xffffffffu, m0, 1));
            m1 = fmaxf(m1, __shfl_xor_sync(0xffffffffu, m1, 1));
            if (!(lane & 1)) {
                int pi = ((tile0 + ng_off + ns * 8) >> 2) + ((lane & 3) >> 1);
                if (pi < Lpool) {
                    out[((size_t)b * COUT + co0) * Lpool + pi] = m0;
                    out[((size_t)b * COUT + co1) * Lpool + pi] = m1;
                }
            }
        }
    }
}

// ---------------- conv4 + BN + ReLU + mean (atomic into feat) ----------------
__global__ __launch_bounds__(256) void conv4_mma_mean(
    const uint4* __restrict__ Ap, const float* __restrict__ bb,
    const float* __restrict__ in, float* __restrict__ feat)
{
    constexpr int CIN = 128, KSTEPS = 128, NSW = 16;
    constexpr int Lc = 187, RS = 144, JW = 136;
    extern __shared__ float s_in[];     // 128 * 144

    const int b = blockIdx.y;
    const int tile0 = blockIdx.x * 128;
    const int tid = threadIdx.x;

    const float* inb = in + (size_t)b * CIN * Lc;
    for (int idx = tid; idx < CIN * JW; idx += 256) {
        int ci = idx / JW;
        int j = idx - ci * JW;
        int p = tile0 - 3 + j;
        s_in[ci * RS + j] = (p >= 0 && p < Lc) ? inb[ci * Lc + p] : 0.0f;
    }
    __syncthreads();

    const int wid = tid >> 5, lane = tid & 31;
    const int mt = wid;
    const unsigned* sp = (const unsigned*)s_in;

    float acc[NSW][4] = {};
    const int boff = (lane >> 2) + (lane & 3);

    for (int ks = 0; ks < KSTEPS; ks++) {
        uint4 a = Ap[(mt * KSTEPS + ks) * 32 + lane];
        const unsigned* srow = sp + ks * RS + boff;
        #pragma unroll
        for (int ns = 0; ns < NSW; ns++) {
            unsigned b0 = srow[ns * 8];
            unsigned b1 = srow[ns * 8 + 4];
            mma_tf32(acc[ns], a, b0, b1);
        }
    }

    const int row0 = lane >> 2;
    const int co0 = mt * 16 + row0;
    const int co1 = co0 + 8;
    const float bv0 = bb[co0], bv1 = bb[co1];
    float s0 = 0.f, s1 = 0.f;

    #pragma unroll
    for (int ns = 0; ns < NSW; ns++) {
        int pos = tile0 + ns * 8 + 2 * (lane & 3);
        if (pos < Lc) {
            s0 += fmaxf(acc[ns][0] + bv0, 0.f);
            s1 += fmaxf(acc[ns][2] + bv1, 0.f);
        }
        if (pos + 1 < Lc) {
            s0 += fmaxf(acc[ns][1] + bv0, 0.f);
            s1 += fmaxf(acc[ns][3] + bv1, 0.f);
        }
    }
    s0 += __shfl_xor_sync(0xffffffffu, s0, 1);
    s0 += __shfl_xor_sync(0xffffffffu, s0, 2);
    s1 += __shfl_xor_sync(0xffffffffu, s1, 1);
    s1 += __shfl_xor_sync(0xffffffffu, s1, 2);
    if ((lane & 3) == 0) {
        atomicAdd(feat + b * 128 + co0, s0);
        atomicAdd(feat + b * 128 + co1, s1);
    }
}

// ---------------- fc(128->128)+relu, ang(128->8), angles = pi*tanh ----------
__global__ void head_kernel(const float* __restrict__ feat,
                            const float* __restrict__ fcw, const float* __restrict__ fcb,
                            const float* __restrict__ angw, const float* __restrict__ angb,
                            float* __restrict__ ang)
{
    int b = blockIdx.x, tid = threadIdx.x;  // 128 threads
    __shared__ float f[128];
    __shared__ float h[128];
    f[tid] = feat[b * 128 + tid] * (1.0f / 187.0f);
    __syncthreads();
    float a = fcb[tid];
    const float* wr = fcw + tid * 128;
    #pragma unroll 8
    for (int k = 0; k < 128; k++) a = fmaf(wr[k], f[k], a);
    h[tid] = fmaxf(a, 0.f);
    __syncthreads();
    if (tid < NQ_) {
        float r = angb[tid];
        const float* ar = angw + tid * 128;
        #pragma unroll 8
        for (int k = 0; k < 128; k++) r = fmaf(ar[k], h[k], r);
        ang[b * NQ_ + tid] = 3.14159265358979323846f * tanhf(r);
    }
}

// ---------------- 8-qubit statevector sim + PauliZ + MLP head ----------------
__device__ __forceinline__ float2 cmul(float2 a, float2 b) {
    return make_float2(a.x * b.x - a.y * b.y, a.x * b.y + a.y * b.x);
}
__device__ __forceinline__ float2 cadd(float2 a, float2 b) {
    return make_float2(a.x + b.x, a.y + b.y);
}

__global__ void qsim_kernel(const float* __restrict__ ang, const float* __restrict__ qw,
                            const float* __restrict__ h1w, const float* __restrict__ h1b,
                            const float* __restrict__ h2w, const float* __restrict__ h2b,
                            float* __restrict__ out)
{
    int b = blockIdx.x, i = threadIdx.x;  // 256 threads, one amplitude each
    __shared__ float2 st[256];
    st[i] = make_float2(i == 0 ? 1.f : 0.f, 0.f);
    __syncthreads();

    for (int wq = 0; wq < NQ_; wq++) {
        int m = 1 << (7 - wq);
        float a = 0.5f * ang[b * NQ_ + wq];
        float c = cosf(a), s = sinf(a);
        if ((i & m) == 0) {
            float2 a0 = st[i], a1 = st[i | m];
            st[i]     = make_float2(c * a0.x - s * a1.x, c * a0.y - s * a1.y);
            st[i | m] = make_float2(s * a0.x + c * a1.x, s * a0.y + c * a1.y);
        }
        __syncthreads();
    }

    for (int l = 0; l < NL_; l++) {
        for (int wq = 0; wq < NQ_; wq++) {
            int m = 1 << (7 - wq);
            const float* p = qw + (l * NQ_ + wq) * 3;
            float phi = p[0], th = p[1], om = p[2];
            float cm = cosf(0.5f * th), sm = sinf(0.5f * th);
            float hpo = 0.5f * (phi + om), hpm = 0.5f * (phi - om);
            float2 m00 = make_float2( cm * cosf(hpo), -cm * sinf(hpo));
            float2 m01 = make_float2(-sm * cosf(hpm), -sm * sinf(hpm));
            float2 m10 = make_float2( sm * cosf(hpm), -sm * sinf(hpm));
            float2 m11 = make_float2( cm * cosf(hpo),  cm * sinf(hpo));
            if ((i & m) == 0) {
                float2 a0 = st[i], a1 = st[i | m];
                st[i]     = cadd(cmul(m00, a0), cmul(m01, a1));
                st[i | m] = cadd(cmul(m10, a0), cmul(m11, a1));
            }
            __syncthreads();
        }
        int r = (l % (NQ_ - 1)) + 1;
        for (int q = 0; q < NQ_; q++) {
            int c = q, t = (q + r) & 7;
            int mc = 1 << (7 - c), mt = 1 << (7 - t);
            if ((i & mc) && !(i & mt)) {
                float2 tmp = st[i];
                st[i] = st[i | mt];
                st[i | mt] = tmp;
            }
            __syncthreads();
        }
    }

    __shared__ float pr[256];
    pr[i] = st[i].x * st[i].x + st[i].y * st[i].y;
    __syncthreads();

    __shared__ float z[NQ_];
    if (i < NQ_) {
        float s = 0.f;
        int sh = 7 - i;
        for (int j = 0; j < 256; j++) s += ((j >> sh) & 1) ? -pr[j] : pr[j];
        z[i] = s;
    }
    __syncthreads();

    __shared__ float h1[64];
    if (i < 64) {
        float a = h1b[i];
        #pragma unroll
        for (int k = 0; k < NQ_; k++) a = fmaf(h1w[i * NQ_ + k], z[k], a);
        h1[i] = fmaxf(a, 0.f);
    }
    __syncthreads();

    if (i < NCLS_) {
        float a = h2b[i];
        #pragma unroll 8
        for (int k = 0; k < 64; k++) a = fmaf(h2w[i * 64 + k], h1[k], a);
        out[b * NCLS_ + i] = a;
    }
}

// ---------------- launch ----------------
extern "C" void kernel_launch(void* const* d_in, const int* in_sizes, int n_in,
                              void* d_out, int out_size)
{
    const float* x       = (const float*)d_in[0];
    const float* conv1_w = (const float*)d_in[1];
    const float* conv1_b = (const float*)d_in[2];
    const float* bn1_g   = (const float*)d_in[3];
    const float* bn1_b   = (const float*)d_in[4];
    const float* conv2_w = (const float*)d_in[5];
    const float* conv2_b = (const float*)d_in[6];
    const float* bn2_g   = (const float*)d_in[7];
    const float* bn2_b   = (const float*)d_in[8];
    const float* conv3_w = (const float*)d_in[9];
    const float* conv3_b = (const float*)d_in[10];
    const float* bn3_g   = (const float*)d_in[11];
    const float* bn3_b   = (const float*)d_in[12];
    const float* conv4_w = (const float*)d_in[13];
    const float* conv4_b = (const float*)d_in[14];
    const float* bn4_g   = (const float*)d_in[15];
    const float* bn4_b   = (const float*)d_in[16];
    const float* fc_w    = (const float*)d_in[17];
    const float* fc_b    = (const float*)d_in[18];
    const float* ang_w   = (const float*)d_in[19];
    const float* ang_b   = (const float*)d_in[20];
    const float* qw      = (const float*)d_in[21];
    const float* h1_w    = (const float*)d_in[22];
    const float* h1_b    = (const float*)d_in[23];
    const float* h2_w    = (const float*)d_in[24];
    const float* h2_b    = (const float*)d_in[25];
    float* out = (float*)d_out;

    float *b1, *b2, *b3, *feat, *ang;
    uint4 *ap1, *ap2, *ap3, *ap4;
    float *bb1, *bb2, *bb3, *bb4;
    cudaGetSymbolAddress((void**)&b1, g_buf1);
    cudaGetSymbolAddress((void**)&b2, g_buf2);
    cudaGetSymbolAddress((void**)&b3, g_buf3);
    cudaGetSymbolAddress((void**)&feat, g_feat);
    cudaGetSymbolAddress((void**)&ang, g_ang);
    cudaGetSymbolAddress((void**)&ap1, g_ap1);
    cudaGetSymbolAddress((void**)&ap2, g_ap2);
    cudaGetSymbolAddress((void**)&ap3, g_ap3);
    cudaGetSymbolAddress((void**)&ap4, g_ap4);
    cudaGetSymbolAddress((void**)&bb1, g_bb1);
    cudaGetSymbolAddress((void**)&bb2, g_bb2);
    cudaGetSymbolAddress((void**)&bb3, g_bb3);
    cudaGetSymbolAddress((void**)&bb4, g_bb4);

    // prepack weights + zero feat accumulator
    prep_all<<<(128 * 128 * 8 + 255) / 256, 256>>>(
        conv1_w, conv1_b, bn1_g, bn1_b, conv2_w, conv2_b, bn2_g, bn2_b,
        conv3_w, conv3_b, bn3_g, bn3_b, conv4_w, conv4_b, bn4_g, bn4_b,
        (unsigned*)ap1, bb1, (unsigned*)ap2, bb2,
        (unsigned*)ap3, bb3, (unsigned*)ap4, bb4, feat);

    size_t sm1 = (size_t)4   * 144 * 4;
    size_t sm2 = (size_t)32  * 144 * 4;
    size_t sm3 = (size_t)64  * 144 * 4;   // 36864
    size_t sm4 = (size_t)128 * 144 * 4;   // 73728 > 48KB

    cudaFuncSetAttribute(conv4_mma_mean,
                         cudaFuncAttributeMaxDynamicSharedMemorySize, (int)sm4);

    // conv1: (B,4,3000) -> (B,32,3000)
    conv_mma<4, 32, 0><<<dim3(24, B_), 256, sm1>>>(ap1, bb1, x, b1, 3000, 3000, 0);
    // conv2 + pool4: -> (B,64,750)
    conv_mma<32, 64, 4><<<dim3(24, B_), 256, sm2>>>(ap2, bb2, b1, b2, 3000, 3000, 750);
    // conv3 + pool4: -> (B,128,187)
    conv_mma<64, 128, 4><<<dim3(6, B_), 256, sm3>>>(ap3, bb3, b2, b3, 750, 750, 187);
    // conv4 + mean (atomic) -> feat sums
    conv4_mma_mean<<<dim3(2, B_), 256, sm4>>>(ap4, bb4, b3, feat);
    // fc + ang head -> angles (B,8)   (divides feat by 187)
    head_kernel<<<B_, 128>>>(feat, fc_w, fc_b, ang_w, ang_b, ang);
    // quantum sim + final MLP -> (B,5)
    qsim_kernel<<<B_, 256>>>(ang, qw, h1_w, h1_b, h2_w, h2_b, out);
}

// round 5
// speedup vs baseline: 8.3659x; 1.5176x over previous
#include <cuda_runtime.h>
#include <cuda_bf16.h>
#include <math.h>

#define B_ 256
#define NQ_ 8
#define NL_ 2
#define NCLS_ 5

// ---------------- scratch buffers (bf16 intermediates) ----------------
__device__ unsigned       g_buf1[B_ * 32 * 1500];   // conv1 out: bf16, row stride 3000 halfs
__device__ unsigned short g_buf2[B_ * 64 * 752];    // conv2+pool out: stride 752, len 750
__device__ unsigned short g_buf3[B_ * 128 * 188];   // conv3+pool out: stride 188, len 187
__device__ float g_feat[B_ * 128];                  // conv4 sums (atomic)
__device__ float g_ang[B_ * NQ_];                   // angles

// fragment-ordered bf16 weights: [(mt*KS2+ks2)*32+lane] -> uint4 {a0,a1,a2,a3}
__device__ uint4 g_ap1[2 * 2 * 32];                 // (COUT/16) * (CIN/2) * 32
__device__ uint4 g_ap2[4 * 16 * 32];
__device__ uint4 g_ap3[8 * 32 * 32];
__device__ uint4 g_ap4[8 * 64 * 32];
__device__ float g_bb1[32], g_bb2[64], g_bb3[128], g_bb4[128];

// ---------------- helpers ----------------
__device__ __forceinline__ unsigned pk_bf16(float lo, float hi) {
    unsigned r;
    asm("cvt.rn.bf16x2.f32 %0,%1,%2;" : "=r"(r) : "f"(hi), "f"(lo));
    return r;
}

// load aligned bf16 word W (halfs 2W, 2W+1) from a row of Lh valid halfs; OOR -> 0
__device__ __forceinline__ unsigned ldw(const unsigned short* row, int W, int Lh) {
    int h0 = 2 * W;
    if (W >= 0 && h0 + 1 < Lh) return ((const unsigned*)row)[W];
    unsigned lo = (h0 >= 0 && h0 < Lh) ? row[h0] : 0u;
    unsigned hi = (h0 + 1 >= 0 && h0 + 1 < Lh) ? row[h0 + 1] : 0u;
    return lo | (hi << 16);
}

__device__ __forceinline__ void mma_bf16(float* d, const uint4& a,
                                         unsigned b0, unsigned b1)
{
    asm volatile(
        "mma.sync.aligned.m16n8k16.row.col.f32.bf16.bf16.f32 "
        "{%0,%1,%2,%3},{%4,%5,%6,%7},{%8,%9},{%0,%1,%2,%3};"
        : "+f"(d[0]), "+f"(d[1]), "+f"(d[2]), "+f"(d[3])
        : "r"(a.x), "r"(a.y), "r"(a.z), "r"(a.w), "r"(b0), "r"(b1));
}

// ---------------- prepack: BN-fold, bf16, fragment order ----------------
__device__ __forceinline__ float wget(const float* w, int co, int ci, int k,
                                      int CIN, float sc) {
    return (k < 7) ? w[(co * CIN + ci) * 7 + k] * sc : 0.0f;
}

__device__ void prep_one(const float* w, const float* cb, const float* bng,
                         const float* bnb, uint4* ap, float* bbo,
                         int CIN, int COUT, int idx)
{
    const float inv = rsqrtf(1.0f + 1e-5f);
    int KS2 = CIN / 2;
    int total = (COUT / 16) * KS2 * 32;
    if (idx < total) {
        int lane = idx & 31, t = idx >> 5;
        int ks2 = t % KS2, mt = t / KS2;
        int r = lane >> 2, c = lane & 3;
        int co = mt * 16 + r;
        int ci0 = 2 * ks2, ci1 = ci0 + 1;
        int k0 = 2 * c, k1 = 2 * c + 1;
        float sc0 = bng[co] * inv, sc8 = bng[co + 8] * inv;
        uint4 a;
        a.x = pk_bf16(wget(w, co,     ci0, k0, CIN, sc0), wget(w, co,     ci0, k1, CIN, sc0));
        a.y = pk_bf16(wget(w, co + 8, ci0, k0, CIN, sc8), wget(w, co + 8, ci0, k1, CIN, sc8));
        a.z = pk_bf16(wget(w, co,     ci1, k0, CIN, sc0), wget(w, co,     ci1, k1, CIN, sc0));
        a.w = pk_bf16(wget(w, co + 8, ci1, k0, CIN, sc8), wget(w, co + 8, ci1, k1, CIN, sc8));
        ap[idx] = a;
    }
    if (idx < COUT) {
        float sc = bng[idx] * inv;
        bbo[idx] = cb[idx] * sc + bnb[idx];
    }
}

__global__ void prep_all(
    const float* w1, const float* b1, const float* g1, const float* be1,
    const float* w2, const float* b2, const float* g2, const float* be2,
    const float* w3, const float* b3, const float* g3, const float* be3,
    const float* w4, const float* b4, const float* g4, const float* be4,
    uint4* ap1, float* bb1, uint4* ap2, float* bb2,
    uint4* ap3, float* bb3, uint4* ap4, float* bb4, float* feat)
{
    int idx = blockIdx.x * blockDim.x + threadIdx.x;
    prep_one(w1, b1, g1, be1, ap1, bb1, 4, 32, idx);
    prep_one(w2, b2, g2, be2, ap2, bb2, 32, 64, idx);
    prep_one(w3, b3, g3, be3, ap3, bb3, 64, 128, idx);
    prep_one(w4, b4, g4, be4, ap4, bb4, 128, 128, idx);
    if (idx < B_ * 128) feat[idx] = 0.0f;
}

// ---------------- conv1d(k=7,pad=3)+BN+ReLU(+maxpool4), bf16 implicit GEMM ---
// smem per ci row: 144 words = [copy0: 72 words (even-aligned pairs)][copy1: 72 (shift 1)]
// MODE 0: store bf16 words; MODE 4: maxpool4 + bf16 scalar store.
template<int CIN, int COUT, int MODE, bool F32IN>
__global__ __launch_bounds__(256) void conv_mma(
    const uint4* __restrict__ Ap, const float* __restrict__ bb,
    const void* __restrict__ in_, void* __restrict__ out_,
    int Lh, int LSTRin, int Lout, int LSTRout)
{
    constexpr int WM = COUT / 16;
    constexpr int WN = 8 / WM;
    constexpr int NSW = 16 / WN;
    constexpr int KS2 = CIN / 2;
    constexpr int RS = 144;
    extern __shared__ unsigned sw[];   // CIN * RS words

    const int b = blockIdx.y;
    const int tile0 = blockIdx.x * 128;
    const int tid = threadIdx.x;

    // producer: bf16 dual-copy tile, global-word aligned (base half = tile0-4)
    if (F32IN) {
        const float* inb = (const float*)in_ + (size_t)b * CIN * LSTRin;
        for (int idx = tid; idx < CIN * 69; idx += 256) {
            int ci = idx / 69, j = idx - ci * 69;
            int g = tile0 - 4 + 2 * j;
            const float* row = inb + ci * LSTRin;
            float x0 = (g >= 0 && g < Lh) ? row[g] : 0.f;
            float x1 = (g + 1 >= 0 && g + 1 < Lh) ? row[g + 1] : 0.f;
            float x2 = (g + 2 >= 0 && g + 2 < Lh) ? row[g + 2] : 0.f;
            sw[ci * RS + j]      = pk_bf16(x0, x1);
            sw[ci * RS + 72 + j] = pk_bf16(x1, x2);
        }
    } else {
        const unsigned short* inb = (const unsigned short*)in_ + (size_t)b * CIN * LSTRin;
        for (int idx = tid; idx < CIN * 69; idx += 256) {
            int ci = idx / 69, j = idx - ci * 69;
            int W0 = ((tile0 - 4) >> 1) + j;
            const unsigned short* row = inb + ci * LSTRin;
            unsigned wa = ldw(row, W0, Lh);
            unsigned wb = ldw(row, W0 + 1, Lh);
            sw[ci * RS + j]      = wa;
            sw[ci * RS + 72 + j] = (wa >> 16) | (wb << 16);
        }
    }
    __syncthreads();

    const int wid = tid >> 5, lane = tid & 31;
    const int mt = wid % WM;
    const int ng_off = (wid / WM) * (NSW * 8);
    const int gid = lane >> 2, tid4 = lane & 3;

    // B-frag base: half index h0 = ng_off + gid + 2*tid4 + 1 (shifted grid)
    const int h0 = ng_off + gid + 2 * tid4 + 1;
    const int off0 = (h0 >> 1) + ((h0 & 1) ? 72 : 0);

    float acc[NSW][4] = {};

    for (int ks2 = 0; ks2 < KS2; ks2++) {
        uint4 a = Ap[(mt * KS2 + ks2) * 32 + lane];
        const unsigned* s0 = sw + (2 * ks2) * RS + off0;
        #pragma unroll
        for (int ns = 0; ns < NSW; ns++) {
            unsigned b0 = s0[ns * 4];
            unsigned b1 = s0[RS + ns * 4];
            mma_bf16(acc[ns], a, b0, b1);
        }
    }

    // epilogue
    const int co0 = mt * 16 + gid;
    const int co1 = co0 + 8;
    const float bv0 = bb[co0], bv1 = bb[co1];

    #pragma unroll
    for (int ns = 0; ns < NSW; ns++) {
        int pos = tile0 + ng_off + ns * 8 + 2 * tid4;
        if (MODE == 0) {
            if (pos < Lout) {
                float y0 = fmaxf(acc[ns][0] + bv0, 0.f);
                float y1 = fmaxf(acc[ns][1] + bv0, 0.f);
                float y2 = fmaxf(acc[ns][2] + bv1, 0.f);
                float y3 = fmaxf(acc[ns][3] + bv1, 0.f);
                unsigned* ow = (unsigned*)out_;
                ow[((size_t)b * COUT + co0) * (LSTRout >> 1) + (pos >> 1)] = pk_bf16(y0, y1);
                ow[((size_t)b * COUT + co1) * (LSTRout >> 1) + (pos >> 1)] = pk_bf16(y2, y3);
            }
        } else {
            float m0 = fmaxf(fmaxf(acc[ns][0], acc[ns][1]) + bv0, 0.f);
            float m1 = fmaxf(fmaxf(acc[ns][2], acc[ns][3]) + bv1, 0.f);
            m0 = fmaxf(m0, __shfl_xor_sync(0xffffffffu, m0, 1));
            m1 = fmaxf(m1, __shfl_xor_sync(0xffffffffu, m1, 1));
            if (!(lane & 1)) {
                int pi = ((tile0 + ng_off + ns * 8) >> 2) + (tid4 >> 1);
                if (pi < Lout) {
                    unsigned short* oh = (unsigned short*)out_;
                    __nv_bfloat16 h0b = __float2bfloat16_rn(m0);
                    __nv_bfloat16 h1b = __float2bfloat16_rn(m1);
                    oh[((size_t)b * COUT + co0) * LSTRout + pi] = *(unsigned short*)&h0b;
                    oh[((size_t)b * COUT + co1) * LSTRout + pi] = *(unsigned short*)&h1b;
                }
            }
        }
    }
}

// ---------------- conv4 + BN + ReLU + mean (atomic into feat), bf16 ----------
__global__ __launch_bounds__(256) void conv4_mma_mean(
    const uint4* __restrict__ Ap, const float* __restrict__ bb,
    const unsigned short* __restrict__ in, float* __restrict__ feat)
{
    constexpr int CIN = 128, KS2 = 64, NSW = 16;
    constexpr int Lc = 187, LSTR = 188, RS = 144;
    extern __shared__ unsigned sw[];   // 128 * 144 words

    const int b = blockIdx.y;
    const int tile0 = blockIdx.x * 128;
    const int tid = threadIdx.x;

    const unsigned short* inb = in + (size_t)b * CIN * LSTR;
    for (int idx = tid; idx < CIN * 69; idx += 256) {
        int ci = idx / 69, j = idx - ci * 69;
        int W0 = ((tile0 - 4) >> 1) + j;
        const unsigned short* row = inb + ci * LSTR;
        unsigned wa = ldw(row, W0, Lc);
        unsigned wb = ldw(row, W0 + 1, Lc);
        sw[ci * RS + j]      = wa;
        sw[ci * RS + 72 + j] = (wa >> 16) | (wb << 16);
    }
    __syncthreads();

    const int wid = tid >> 5, lane = tid & 31;
    const int gid = lane >> 2, tid4 = lane & 3;
    const int h0 = gid + 2 * tid4 + 1;
    const int off0 = (h0 >> 1) + ((h0 & 1) ? 72 : 0);

    float acc[NSW][4] = {};

    for (int ks2 = 0; ks2 < KS2; ks2++) {
        uint4 a = Ap[(wid * KS2 + ks2) * 32 + lane];
        const unsigned* s0 = sw + (2 * ks2) * RS + off0;
        #pragma unroll
        for (int ns = 0; ns < NSW; ns++) {
            unsigned b0 = s0[ns * 4];
            unsigned b1 = s0[RS + ns * 4];
            mma_bf16(acc[ns], a, b0, b1);
        }
    }

    const int co0 = wid * 16 + gid;
    const int co1 = co0 + 8;
    const float bv0 = bb[co0], bv1 = bb[co1];
    float s0 = 0.f, s1 = 0.f;

    #pragma unroll
    for (int ns = 0; ns < NSW; ns++) {
        int pos = tile0 + ns * 8 + 2 * tid4;
        if (pos < Lc) {
            s0 += fmaxf(acc[ns][0] + bv0, 0.f);
            s1 += fmaxf(acc[ns][2] + bv1, 0.f);
        }
        if (pos + 1 < Lc) {
            s0 += fmaxf(acc[ns][1] + bv0, 0.f);
            s1 += fmaxf(acc[ns][3] + bv1, 0.f);
        }
    }
    s0 += __shfl_xor_sync(0xffffffffu, s0, 1);
    s0 += __shfl_xor_sync(0xffffffffu, s0, 2);
    s1 += __shfl_xor_sync(0xffffffffu, s1, 1);
    s1 += __shfl_xor_sync(0xffffffffu, s1, 2);
    if ((lane & 3) == 0) {
        atomicAdd(feat + b * 128 + co0, s0);
        atomicAdd(feat + b * 128 + co1, s1);
    }
}

// ---------------- fc(128->128)+relu, ang(128->8), angles = pi*tanh ----------
__global__ void head_kernel(const float* __restrict__ feat,
                            const float* __restrict__ fcw, const float* __restrict__ fcb,
                            const float* __restrict__ angw, const float* __restrict__ angb,
                            float* __restrict__ ang)
{
    int b = blockIdx.x, tid = threadIdx.x;  // 128 threads
    __shared__ float f[128];
    __shared__ float h[128];
    f[tid] = feat[b * 128 + tid] * (1.0f / 187.0f);
    __syncthreads();
    float a = fcb[tid];
    const float* wr = fcw + tid * 128;
    #pragma unroll 8
    for (int k = 0; k < 128; k++) a = fmaf(wr[k], f[k], a);
    h[tid] = fmaxf(a, 0.f);
    __syncthreads();
    if (tid < NQ_) {
        float r = angb[tid];
        const float* ar = angw + tid * 128;
        #pragma unroll 8
        for (int k = 0; k < 128; k++) r = fmaf(ar[k], h[k], r);
        ang[b * NQ_ + tid] = 3.14159265358979323846f * tanhf(r);
    }
}

// ---------------- 8-qubit statevector sim + PauliZ + MLP head ----------------
__device__ __forceinline__ float2 cmul(float2 a, float2 b) {
    return make_float2(a.x * b.x - a.y * b.y, a.x * b.y + a.y * b.x);
}
__device__ __forceinline__ float2 cadd(float2 a, float2 b) {
    return make_float2(a.x + b.x, a.y + b.y);
}

__global__ void qsim_kernel(const float* __restrict__ ang, const float* __restrict__ qw,
                            const float* __restrict__ h1w, const float* __restrict__ h1b,
                            const float* __restrict__ h2w, const float* __restrict__ h2b,
                            float* __restrict__ out)
{
    int b = blockIdx.x, i = threadIdx.x;  // 256 threads, one amplitude each
    __shared__ float2 st[256];
    st[i] = make_float2(i == 0 ? 1.f : 0.f, 0.f);
    __syncthreads();

    for (int wq = 0; wq < NQ_; wq++) {
        int m = 1 << (7 - wq);
        float a = 0.5f * ang[b * NQ_ + wq];
        float c = cosf(a), s = sinf(a);
        if ((i & m) == 0) {
            float2 a0 = st[i], a1 = st[i | m];
            st[i]     = make_float2(c * a0.x - s * a1.x, c * a0.y - s * a1.y);
            st[i | m] = make_float2(s * a0.x + c * a1.x, s * a0.y + c * a1.y);
        }
        __syncthreads();
    }

    for (int l = 0; l < NL_; l++) {
        for (int wq = 0; wq < NQ_; wq++) {
            int m = 1 << (7 - wq);
            const float* p = qw + (l * NQ_ + wq) * 3;
            float phi = p[0], th = p[1], om = p[2];
            float cm = cosf(0.5f * th), sm = sinf(0.5f * th);
            float hpo = 0.5f * (phi + om), hpm = 0.5f * (phi - om);
            float2 m00 = make_float2( cm * cosf(hpo), -cm * sinf(hpo));
            float2 m01 = make_float2(-sm * cosf(hpm), -sm * sinf(hpm));
            float2 m10 = make_float2( sm * cosf(hpm), -sm * sinf(hpm));
            float2 m11 = make_float2( cm * cosf(hpo),  cm * sinf(hpo));
            if ((i & m) == 0) {
                float2 a0 = st[i], a1 = st[i | m];
                st[i]     = cadd(cmul(m00, a0), cmul(m01, a1));
                st[i | m] = cadd(cmul(m10, a0), cmul(m11, a1));
            }
            __syncthreads();
        }
        int r = (l % (NQ_ - 1)) + 1;
        for (int q = 0; q < NQ_; q++) {
            int c = q, t = (q + r) & 7;
            int mc = 1 << (7 - c), mt = 1 << (7 - t);
            if ((i & mc) && !(i & mt)) {
                float2 tmp = st[i];
                st[i] = st[i | mt];
                st[i | mt] = tmp;
            }
            __syncthreads();
        }
    }

    // PauliZ expectations via warp reductions
    float p = st[i].x * st[i].x + st[i].y * st[i].y;
    __shared__ float zpart[8][8];   // [warp][wq]
    int warp = i >> 5, lane = i & 31;
    #pragma unroll
    for (int wq = 0; wq < NQ_; wq++) {
        float v = ((i >> (7 - wq)) & 1) ? -p : p;
        #pragma unroll
        for (int o = 16; o; o >>= 1) v += __shfl_down_sync(0xffffffffu, v, o);
        if (lane == 0) zpart[warp][wq] = v;
    }
    __syncthreads();

    __shared__ float z[NQ_];
    if (i < NQ_) {
        float s = 0.f;
        #pragma unroll
        for (int w = 0; w < 8; w++) s += zpart[w][i];
        z[i] = s;
    }
    __syncthreads();

    __shared__ float h1[64];
    if (i < 64) {
        float a = h1b[i];
        #pragma unroll
        for (int k = 0; k < NQ_; k++) a = fmaf(h1w[i * NQ_ + k], z[k], a);
        h1[i] = fmaxf(a, 0.f);
    }
    __syncthreads();

    if (i < NCLS_) {
        float a = h2b[i];
        #pragma unroll 8
        for (int k = 0; k < 64; k++) a = fmaf(h2w[i * 64 + k], h1[k], a);
        out[b * NCLS_ + i] = a;
    }
}

// ---------------- launch ----------------
extern "C" void kernel_launch(void* const* d_in, const int* in_sizes, int n_in,
                              void* d_out, int out_size)
{
    const float* x       = (const float*)d_in[0];
    const float* conv1_w = (const float*)d_in[1];
    const float* conv1_b = (const float*)d_in[2];
    const float* bn1_g   = (const float*)d_in[3];
    const float* bn1_b   = (const float*)d_in[4];
    const float* conv2_w = (const float*)d_in[5];
    const float* conv2_b = (const float*)d_in[6];
    const float* bn2_g   = (const float*)d_in[7];
    const float* bn2_b   = (const float*)d_in[8];
    const float* conv3_w = (const float*)d_in[9];
    const float* conv3_b = (const float*)d_in[10];
    const float* bn3_g   = (const float*)d_in[11];
    const float* bn3_b   = (const float*)d_in[12];
    const float* conv4_w = (const float*)d_in[13];
    const float* conv4_b = (const float*)d_in[14];
    const float* bn4_g   = (const float*)d_in[15];
    const float* bn4_b   = (const float*)d_in[16];
    const float* fc_w    = (const float*)d_in[17];
    const float* fc_b    = (const float*)d_in[18];
    const float* ang_w   = (const float*)d_in[19];
    const float* ang_b   = (const float*)d_in[20];
    const float* qw      = (const float*)d_in[21];
    const float* h1_w    = (const float*)d_in[22];
    const float* h1_b    = (const float*)d_in[23];
    const float* h2_w    = (const float*)d_in[24];
    const float* h2_b    = (const float*)d_in[25];
    float* out = (float*)d_out;

    unsigned* b1; unsigned short *b2, *b3;
    float *feat, *ang;
    uint4 *ap1, *ap2, *ap3, *ap4;
    float *bb1, *bb2, *bb3, *bb4;
    cudaGetSymbolAddress((void**)&b1, g_buf1);
    cudaGetSymbolAddress((void**)&b2, g_buf2);
    cudaGetSymbolAddress((void**)&b3, g_buf3);
    cudaGetSymbolAddress((void**)&feat, g_feat);
    cudaGetSymbolAddress((void**)&ang, g_ang);
    cudaGetSymbolAddress((void**)&ap1, g_ap1);
    cudaGetSymbolAddress((void**)&ap2, g_ap2);
    cudaGetSymbolAddress((void**)&ap3, g_ap3);
    cudaGetSymbolAddress((void**)&ap4, g_ap4);
    cudaGetSymbolAddress((void**)&bb1, g_bb1);
    cudaGetSymbolAddress((void**)&bb2, g_bb2);
    cudaGetSymbolAddress((void**)&bb3, g_bb3);
    cudaGetSymbolAddress((void**)&bb4, g_bb4);

    // prepack weights + zero feat accumulator (needs >= 32768 threads)
    prep_all<<<128, 256>>>(
        conv1_w, conv1_b, bn1_g, bn1_b, conv2_w, conv2_b, bn2_g, bn2_b,
        conv3_w, conv3_b, bn3_g, bn3_b, conv4_w, conv4_b, bn4_g, bn4_b,
        ap1, bb1, ap2, bb2, ap3, bb3, ap4, bb4, feat);

    size_t sm1 = (size_t)4   * 144 * 4;
    size_t sm2 = (size_t)32  * 144 * 4;
    size_t sm3 = (size_t)64  * 144 * 4;   // 36864
    size_t sm4 = (size_t)128 * 144 * 4;   // 73728 > 48KB

    cudaFuncSetAttribute(conv4_mma_mean,
                         cudaFuncAttributeMaxDynamicSharedMemorySize, (int)sm4);

    // conv1: (B,4,3000) fp32 -> (B,32,3000) bf16 (word stride 1500)
    conv_mma<4, 32, 0, true><<<dim3(24, B_), 256, sm1>>>(
        ap1, bb1, x, b1, 3000, 3000, 3000, 3000);
    // conv2 + pool4: -> (B,64,750) bf16 stride 752
    conv_mma<32, 64, 4, false><<<dim3(24, B_), 256, sm2>>>(
        ap2, bb2, b1, b2, 3000, 3000, 750, 752);
    // conv3 + pool4: -> (B,128,187) bf16 stride 188
    conv_mma<64, 128, 4, false><<<dim3(6, B_), 256, sm3>>>(
        ap3, bb3, b2, b3, 750, 752, 187, 188);
    // conv4 + mean (atomic) -> feat sums
    conv4_mma_mean<<<dim3(2, B_), 256, sm4>>>(ap4, bb4, b3, feat);
    // fc + ang head -> angles (B,8)   (divides feat by 187)
    head_kernel<<<B_, 128>>>(feat, fc_w, fc_b, ang_w, ang_b, ang);
    // quantum sim + final MLP -> (B,5)
    qsim_kernel<<<B_, 256>>>(ang, qw, h1_w, h1_b, h2_w, h2_b, out);
}

// round 6
// speedup vs baseline: 9.5081x; 1.1365x over previous
#include <cuda_runtime.h>
#include <cuda_bf16.h>
#include <math.h>

#define B_ 256
#define NQ_ 8
#define NL_ 2
#define NCLS_ 5

// ---------------- scratch buffers (bf16 intermediates) ----------------
__device__ unsigned       g_buf1[B_ * 32 * 1500];   // conv1 out: bf16, stride 3000 halfs
__device__ unsigned short g_buf2[B_ * 64 * 752];    // conv2+pool out: stride 752, len 750
__device__ unsigned short g_buf3[B_ * 128 * 188];   // conv3+pool out: stride 188, len 187
__device__ float g_feat[B_ * 128];                  // conv4 sums (atomic)
__device__ float g_ang[B_ * NQ_];                   // angles

// fragment-ordered bf16 weights: [(mt*KS2+ks2)*32+lane] -> uint4 {a0,a1,a2,a3}
__device__ uint4 g_ap1[2 * 2 * 32];                 // (COUT/16) * (CIN/2) * 32
__device__ uint4 g_ap2[4 * 16 * 32];
__device__ uint4 g_ap3[8 * 32 * 32];
__device__ uint4 g_ap4[8 * 64 * 32];
__device__ float g_bb1[32], g_bb2[64], g_bb3[128], g_bb4[128];

// ---------------- helpers ----------------
__device__ __forceinline__ unsigned pk_bf16(float lo, float hi) {
    unsigned r;
    asm("cvt.rn.bf16x2.f32 %0,%1,%2;" : "=r"(r) : "f"(hi), "f"(lo));
    return r;
}

// load aligned bf16 word W (halfs 2W, 2W+1) from a row of Lh valid halfs; OOR -> 0
__device__ __forceinline__ unsigned ldw(const unsigned short* row, int W, int Lh) {
    int h0 = 2 * W;
    if (W >= 0 && h0 + 1 < Lh) return ((const unsigned*)row)[W];
    unsigned lo = (h0 >= 0 && h0 < Lh) ? row[h0] : 0u;
    unsigned hi = (h0 + 1 >= 0 && h0 + 1 < Lh) ? row[h0 + 1] : 0u;
    return lo | (hi << 16);
}

__device__ __forceinline__ void mma_bf16(float* d, const uint4& a,
                                         unsigned b0, unsigned b1)
{
    asm volatile(
        "mma.sync.aligned.m16n8k16.row.col.f32.bf16.bf16.f32 "
        "{%0,%1,%2,%3},{%4,%5,%6,%7},{%8,%9},{%0,%1,%2,%3};"
        : "+f"(d[0]), "+f"(d[1]), "+f"(d[2]), "+f"(d[3])
        : "r"(a.x), "r"(a.y), "r"(a.z), "r"(a.w), "r"(b0), "r"(b1));
}

// ---------------- prepack: BN-fold, bf16, fragment order ----------------
__device__ __forceinline__ float wget(const float* w, int co, int ci, int k,
                                      int CIN, float sc) {
    return (k < 7) ? w[(co * CIN + ci) * 7 + k] * sc : 0.0f;
}

__device__ void prep_one(const float* w, const float* cb, const float* bng,
                         const float* bnb, uint4* ap, float* bbo,
                         int CIN, int COUT, int idx)
{
    const float inv = rsqrtf(1.0f + 1e-5f);
    int KS2 = CIN / 2;
    int total = (COUT / 16) * KS2 * 32;
    if (idx < total) {
        int lane = idx & 31, t = idx >> 5;
        int ks2 = t % KS2, mt = t / KS2;
        int r = lane >> 2, c = lane & 3;
        int co = mt * 16 + r;
        int ci0 = 2 * ks2, ci1 = ci0 + 1;
        int k0 = 2 * c, k1 = 2 * c + 1;
        float sc0 = bng[co] * inv, sc8 = bng[co + 8] * inv;
        uint4 a;
        a.x = pk_bf16(wget(w, co,     ci0, k0, CIN, sc0), wget(w, co,     ci0, k1, CIN, sc0));
        a.y = pk_bf16(wget(w, co + 8, ci0, k0, CIN, sc8), wget(w, co + 8, ci0, k1, CIN, sc8));
        a.z = pk_bf16(wget(w, co,     ci1, k0, CIN, sc0), wget(w, co,     ci1, k1, CIN, sc0));
        a.w = pk_bf16(wget(w, co + 8, ci1, k0, CIN, sc8), wget(w, co + 8, ci1, k1, CIN, sc8));
        ap[idx] = a;
    }
    if (idx < COUT) {
        float sc = bng[idx] * inv;
        bbo[idx] = cb[idx] * sc + bnb[idx];
    }
}

__global__ void prep_all(
    const float* w1, const float* b1, const float* g1, const float* be1,
    const float* w2, const float* b2, const float* g2, const float* be2,
    const float* w3, const float* b3, const float* g3, const float* be3,
    const float* w4, const float* b4, const float* g4, const float* be4,
    uint4* ap1, float* bb1, uint4* ap2, float* bb2,
    uint4* ap3, float* bb3, uint4* ap4, float* bb4, float* feat)
{
    int idx = blockIdx.x * blockDim.x + threadIdx.x;
    prep_one(w1, b1, g1, be1, ap1, bb1, 4, 32, idx);
    prep_one(w2, b2, g2, be2, ap2, bb2, 32, 64, idx);
    prep_one(w3, b3, g3, be3, ap3, bb3, 64, 128, idx);
    prep_one(w4, b4, g4, be4, ap4, bb4, 128, 128, idx);
    if (idx < B_ * 128) feat[idx] = 0.0f;
}

// ---------------- shared tile producer (bf16 dual-copy layout) ----------------
// sw row ci: [copy0: words 0..68 (even pairs)][copy1: words 72..140 (shift 1)]
// base half = tile0 - 4. Fast path when fully interior.
template<int CIN, bool F32IN>
__device__ __forceinline__ void load_tile(
    unsigned* sw, const void* in_, int b, int tile0, int Lh, int LSTRin,
    int wid, int lane)
{
    constexpr int RS = 144;
    const int base = tile0 - 4;
    const bool interior = (base >= 0) && (base + 139 < Lh);

    if (F32IN) {
        const float* inb = (const float*)in_ + (size_t)b * CIN * LSTRin;
        for (int ci = wid; ci < CIN; ci += 8) {
            const float* row = inb + ci * LSTRin;
            unsigned* d = sw + ci * RS;
            if (interior) {
                for (int j = lane; j < 69; j += 32) {
                    int g = base + 2 * j;
                    float2 v = *(const float2*)(row + g);
                    float x2 = row[g + 2];
                    d[j]      = pk_bf16(v.x, v.y);
                    d[72 + j] = pk_bf16(v.y, x2);
                }
            } else {
                for (int j = lane; j < 69; j += 32) {
                    int g = base + 2 * j;
                    float x0 = (g >= 0 && g < Lh) ? row[g] : 0.f;
                    float x1 = (g + 1 >= 0 && g + 1 < Lh) ? row[g + 1] : 0.f;
                    float x2 = (g + 2 >= 0 && g + 2 < Lh) ? row[g + 2] : 0.f;
                    d[j]      = pk_bf16(x0, x1);
                    d[72 + j] = pk_bf16(x1, x2);
                }
            }
        }
    } else {
        const unsigned short* inb = (const unsigned short*)in_ + (size_t)b * CIN * LSTRin;
        for (int ci = wid; ci < CIN; ci += 8) {
            const unsigned short* row = inb + ci * LSTRin;
            unsigned* d = sw + ci * RS;
            if (interior) {
                const unsigned* rw = (const unsigned*)row + (base >> 1);
                for (int j = lane; j < 69; j += 32) {
                    unsigned wa = rw[j], wb = rw[j + 1];
                    d[j]      = wa;
                    d[72 + j] = (wa >> 16) | (wb << 16);
                }
            } else {
                const int W0 = base >> 1;
                for (int j = lane; j < 69; j += 32) {
                    unsigned wa = ldw(row, W0 + j, Lh);
                    unsigned wb = ldw(row, W0 + j + 1, Lh);
                    d[j]      = wa;
                    d[72 + j] = (wa >> 16) | (wb << 16);
                }
            }
        }
    }
}

// ---------------- conv1d(k=7,pad=3)+BN+ReLU(+maxpool4), bf16 implicit GEMM ---
// Warp grid: MW m-warps (each owning MT=2 m-tiles = 32 co) x NG n-groups.
// Each B fragment pair feeds 2 mma (one per m-tile) -> half the smem traffic.
template<int CIN, int COUT, int MODE, bool F32IN>
__global__ __launch_bounds__(256) void conv_mma(
    const uint4* __restrict__ Ap, const float* __restrict__ bb,
    const void* __restrict__ in_, void* __restrict__ out_,
    int Lh, int LSTRin, int Lout, int LSTRout)
{
    constexpr int MW  = COUT / 32;      // m-warps
    constexpr int NG  = 8 / MW;         // n-groups
    constexpr int NSW = 16 / NG;        // n-steps per warp
    constexpr int KS2 = CIN / 2;
    constexpr int RS  = 144;
    extern __shared__ unsigned sw[];    // CIN * RS words

    const int b = blockIdx.y;
    const int tile0 = blockIdx.x * 128;
    const int tid = threadIdx.x;
    const int wid = tid >> 5, lane = tid & 31;

    load_tile<CIN, F32IN>(sw, in_, b, tile0, Lh, LSTRin, wid, lane);
    __syncthreads();

    const int mw = wid % MW, ng = wid / MW;
    const int mt0 = mw * 2, mt1 = mt0 + 1;
    const int ng_off = ng * (NSW * 8);
    const int gid = lane >> 2, tid4 = lane & 3;

    const int h0 = ng_off + gid + 2 * tid4 + 1;
    const int off0 = (h0 >> 1) + ((h0 & 1) ? 72 : 0);

    float acc[2][NSW][4] = {};

    const uint4* A0 = Ap + (size_t)(mt0 * KS2) * 32 + lane;
    const uint4* A1 = Ap + (size_t)(mt1 * KS2) * 32 + lane;
    uint4 a0 = A0[0], a1 = A1[0];

    for (int ks2 = 0; ks2 < KS2; ks2++) {
        const int nk = (ks2 + 1 < KS2) ? ks2 + 1 : ks2;
        uint4 n0 = A0[nk * 32];
        uint4 n1 = A1[nk * 32];
        const unsigned* s0 = sw + (2 * ks2) * RS + off0;
        #pragma unroll
        for (int ns = 0; ns < NSW; ns++) {
            unsigned b0 = s0[ns * 4];
            unsigned b1 = s0[RS + ns * 4];
            mma_bf16(acc[0][ns], a0, b0, b1);
            mma_bf16(acc[1][ns], a1, b0, b1);
        }
        a0 = n0; a1 = n1;
    }

    // epilogue
    #pragma unroll
    for (int m = 0; m < 2; m++) {
        const int mt = (m == 0) ? mt0 : mt1;
        const int co0 = mt * 16 + gid;
        const int co1 = co0 + 8;
        const float bv0 = bb[co0], bv1 = bb[co1];
        #pragma unroll
        for (int ns = 0; ns < NSW; ns++) {
            int pos = tile0 + ng_off + ns * 8 + 2 * tid4;
            if (MODE == 0) {
                if (pos < Lout) {
                    float y0 = fmaxf(acc[m][ns][0] + bv0, 0.f);
                    float y1 = fmaxf(acc[m][ns][1] + bv0, 0.f);
                    float y2 = fmaxf(acc[m][ns][2] + bv1, 0.f);
                    float y3 = fmaxf(acc[m][ns][3] + bv1, 0.f);
                    unsigned* ow = (unsigned*)out_;
                    ow[((size_t)b * COUT + co0) * (LSTRout >> 1) + (pos >> 1)] = pk_bf16(y0, y1);
                    ow[((size_t)b * COUT + co1) * (LSTRout >> 1) + (pos >> 1)] = pk_bf16(y2, y3);
                }
            } else {
                float m0 = fmaxf(fmaxf(acc[m][ns][0], acc[m][ns][1]) + bv0, 0.f);
                float m1 = fmaxf(fmaxf(acc[m][ns][2], acc[m][ns][3]) + bv1, 0.f);
                m0 = fmaxf(m0, __shfl_xor_sync(0xffffffffu, m0, 1));
                m1 = fmaxf(m1, __shfl_xor_sync(0xffffffffu, m1, 1));
                if (!(lane & 1)) {
                    int pi = ((tile0 + ng_off + ns * 8) >> 2) + (tid4 >> 1);
                    if (pi < Lout) {
                        unsigned short* oh = (unsigned short*)out_;
                        __nv_bfloat16 h0b = __float2bfloat16_rn(m0);
                        __nv_bfloat16 h1b = __float2bfloat16_rn(m1);
                        oh[((size_t)b * COUT + co0) * LSTRout + pi] = *(unsigned short*)&h0b;
                        oh[((size_t)b * COUT + co1) * LSTRout + pi] = *(unsigned short*)&h1b;
                    }
                }
            }
        }
    }
}

// ---------------- conv4 + BN + ReLU + mean (atomic into feat), bf16 ----------
__global__ __launch_bounds__(256) void conv4_mma_mean(
    const uint4* __restrict__ Ap, const float* __restrict__ bb,
    const unsigned short* __restrict__ in, float* __restrict__ feat)
{
    constexpr int CIN = 128, KS2 = 64, NSW = 8;
    constexpr int Lc = 187, LSTR = 188, RS = 144;
    extern __shared__ unsigned sw[];

    const int b = blockIdx.y;
    const int tile0 = blockIdx.x * 128;
    const int tid = threadIdx.x;
    const int wid = tid >> 5, lane = tid & 31;

    load_tile<CIN, false>(sw, in, b, tile0, Lc, LSTR, wid, lane);
    __syncthreads();

    const int mw = wid % 4, ng = wid / 4;
    const int mt0 = mw * 2, mt1 = mt0 + 1;
    const int ng_off = ng * (NSW * 8);
    const int gid = lane >> 2, tid4 = lane & 3;
    const int h0 = ng_off + gid + 2 * tid4 + 1;
    const int off0 = (h0 >> 1) + ((h0 & 1) ? 72 : 0);

    float acc[2][NSW][4] = {};

    const uint4* A0 = Ap + (size_t)(mt0 * KS2) * 32 + lane;
    const uint4* A1 = Ap + (size_t)(mt1 * KS2) * 32 + lane;
    uint4 a0 = A0[0], a1 = A1[0];

    for (int ks2 = 0; ks2 < KS2; ks2++) {
        const int nk = (ks2 + 1 < KS2) ? ks2 + 1 : ks2;
        uint4 n0 = A0[nk * 32];
        uint4 n1 = A1[nk * 32];
        const unsigned* s0 = sw + (2 * ks2) * RS + off0;
        #pragma unroll
        for (int ns = 0; ns < NSW; ns++) {
            unsigned b0 = s0[ns * 4];
            unsigned b1 = s0[RS + ns * 4];
            mma_bf16(acc[0][ns], a0, b0, b1);
            mma_bf16(acc[1][ns], a1, b0, b1);
        }
        a0 = n0; a1 = n1;
    }

    #pragma unroll
    for (int m = 0; m < 2; m++) {
        const int mt = (m == 0) ? mt0 : mt1;
        const int co0 = mt * 16 + gid;
        const int co1 = co0 + 8;
        const float bv0 = bb[co0], bv1 = bb[co1];
        float s0 = 0.f, s1 = 0.f;
        #pragma unroll
        for (int ns = 0; ns < NSW; ns++) {
            int pos = tile0 + ng_off + ns * 8 + 2 * tid4;
            if (pos < Lc) {
                s0 += fmaxf(acc[m][ns][0] + bv0, 0.f);
                s1 += fmaxf(acc[m][ns][2] + bv1, 0.f);
            }
            if (pos + 1 < Lc) {
                s0 += fmaxf(acc[m][ns][1] + bv0, 0.f);
                s1 += fmaxf(acc[m][ns][3] + bv1, 0.f);
            }
        }
        s0 += __shfl_xor_sync(0xffffffffu, s0, 1);
        s0 += __shfl_xor_sync(0xffffffffu, s0, 2);
        s1 += __shfl_xor_sync(0xffffffffu, s1, 1);
        s1 += __shfl_xor_sync(0xffffffffu, s1, 2);
        if ((lane & 3) == 0) {
            atomicAdd(feat + b * 128 + co0, s0);
            atomicAdd(feat + b * 128 + co1, s1);
        }
    }
}

// ---------------- fc(128->128)+relu, ang(128->8), angles = pi*tanh ----------
__global__ void head_kernel(const float* __restrict__ feat,
                            const float* __restrict__ fcw, const float* __restrict__ fcb,
                            const float* __restrict__ angw, const float* __restrict__ angb,
                            float* __restrict__ ang)
{
    int b = blockIdx.x, tid = threadIdx.x;  // 128 threads
    __shared__ float f[128];
    __shared__ float h[128];
    f[tid] = feat[b * 128 + tid] * (1.0f / 187.0f);
    __syncthreads();
    float a = fcb[tid];
    const float* wr = fcw + tid * 128;
    #pragma unroll 8
    for (int k = 0; k < 128; k++) a = fmaf(wr[k], f[k], a);
    h[tid] = fmaxf(a, 0.f);
    __syncthreads();
    if (tid < NQ_) {
        float r = angb[tid];
        const float* ar = angw + tid * 128;
        #pragma unroll 8
        for (int k = 0; k < 128; k++) r = fmaf(ar[k], h[k], r);
        ang[b * NQ_ + tid] = 3.14159265358979323846f * tanhf(r);
    }
}

// ---------------- 8-qubit statevector sim + PauliZ + MLP head ----------------
__device__ __forceinline__ float2 cmul(float2 a, float2 b) {
    return make_float2(a.x * b.x - a.y * b.y, a.x * b.y + a.y * b.x);
}
__device__ __forceinline__ float2 cadd(float2 a, float2 b) {
    return make_float2(a.x + b.x, a.y + b.y);
}

__global__ void qsim_kernel(const float* __restrict__ ang, const float* __restrict__ qw,
                            const float* __restrict__ h1w, const float* __restrict__ h1b,
                            const float* __restrict__ h2w, const float* __restrict__ h2b,
                            float* __restrict__ out)
{
    int b = blockIdx.x, i = threadIdx.x;  // 256 threads, one amplitude each
    __shared__ float2 st[256];
    st[i] = make_float2(i == 0 ? 1.f : 0.f, 0.f);
    __syncthreads();

    for (int wq = 0; wq < NQ_; wq++) {
        int m = 1 << (7 - wq);
        float a = 0.5f * ang[b * NQ_ + wq];
        float c = cosf(a), s = sinf(a);
        if ((i & m) == 0) {
            float2 a0 = st[i], a1 = st[i | m];
            st[i]     = make_float2(c * a0.x - s * a1.x, c * a0.y - s * a1.y);
            st[i | m] = make_float2(s * a0.x + c * a1.x, s * a0.y + c * a1.y);
        }
        __syncthreads();
    }

    for (int l = 0; l < NL_; l++) {
        for (int wq = 0; wq < NQ_; wq++) {
            int m = 1 << (7 - wq);
            const float* p = qw + (l * NQ_ + wq) * 3;
            float phi = p[0], th = p[1], om = p[2];
            float cm = cosf(0.5f * th), sm = sinf(0.5f * th);
            float hpo = 0.5f * (phi + om), hpm = 0.5f * (phi - om);
            float2 m00 = make_float2( cm * cosf(hpo), -cm * sinf(hpo));
            float2 m01 = make_float2(-sm * cosf(hpm), -sm * sinf(hpm));
            float2 m10 = make_float2( sm * cosf(hpm), -sm * sinf(hpm));
            float2 m11 = make_float2( cm * cosf(hpo),  cm * sinf(hpo));
            if ((i & m) == 0) {
                float2 a0 = st[i], a1 = st[i | m];
                st[i]     = cadd(cmul(m00, a0), cmul(m01, a1));
                st[i | m] = cadd(cmul(m10, a0), cmul(m11, a1));
            }
            __syncthreads();
        }
        int r = (l % (NQ_ - 1)) + 1;
        for (int q = 0; q < NQ_; q++) {
            int c = q, t = (q + r) & 7;
            int mc = 1 << (7 - c), mt = 1 << (7 - t);
            if ((i & mc) && !(i & mt)) {
                float2 tmp = st[i];
                st[i] = st[i | mt];
                st[i | mt] = tmp;
            }
            __syncthreads();
        }
    }

    float p = st[i].x * st[i].x + st[i].y * st[i].y;
    __shared__ float zpart[8][8];
    int warp = i >> 5, lane = i & 31;
    #pragma unroll
    for (int wq = 0; wq < NQ_; wq++) {
        float v = ((i >> (7 - wq)) & 1) ? -p : p;
        #pragma unroll
        for (int o = 16; o; o >>= 1) v += __shfl_down_sync(0xffffffffu, v, o);
        if (lane == 0) zpart[warp][wq] = v;
    }
    __syncthreads();

    __shared__ float z[NQ_];
    if (i < NQ_) {
        float s = 0.f;
        #pragma unroll
        for (int w = 0; w < 8; w++) s += zpart[w][i];
        z[i] = s;
    }
    __syncthreads();

    __shared__ float h1[64];
    if (i < 64) {
        float a = h1b[i];
        #pragma unroll
        for (int k = 0; k < NQ_; k++) a = fmaf(h1w[i * NQ_ + k], z[k], a);
        h1[i] = fmaxf(a, 0.f);
    }
    __syncthreads();

    if (i < NCLS_) {
        float a = h2b[i];
        #pragma unroll 8
        for (int k = 0; k < 64; k++) a = fmaf(h2w[i * 64 + k], h1[k], a);
        out[b * NCLS_ + i] = a;
    }
}

// ---------------- launch ----------------
extern "C" void kernel_launch(void* const* d_in, const int* in_sizes, int n_in,
                              void* d_out, int out_size)
{
    const float* x       = (const float*)d_in[0];
    const float* conv1_w = (const float*)d_in[1];
    const float* conv1_b = (const float*)d_in[2];
    const float* bn1_g   = (const float*)d_in[3];
    const float* bn1_b   = (const float*)d_in[4];
    const float* conv2_w = (const float*)d_in[5];
    const float* conv2_b = (const float*)d_in[6];
    const float* bn2_g   = (const float*)d_in[7];
    const float* bn2_b   = (const float*)d_in[8];
    const float* conv3_w = (const float*)d_in[9];
    const float* conv3_b = (const float*)d_in[10];
    const float* bn3_g   = (const float*)d_in[11];
    const float* bn3_b   = (const float*)d_in[12];
    const float* conv4_w = (const float*)d_in[13];
    const float* conv4_b = (const float*)d_in[14];
    const float* bn4_g   = (const float*)d_in[15];
    const float* bn4_b   = (const float*)d_in[16];
    const float* fc_w    = (const float*)d_in[17];
    const float* fc_b    = (const float*)d_in[18];
    const float* ang_w   = (const float*)d_in[19];
    const float* ang_b   = (const float*)d_in[20];
    const float* qw      = (const float*)d_in[21];
    const float* h1_w    = (const float*)d_in[22];
    const float* h1_b    = (const float*)d_in[23];
    const float* h2_w    = (const float*)d_in[24];
    const float* h2_b    = (const float*)d_in[25];
    float* out = (float*)d_out;

    unsigned* b1; unsigned short *b2, *b3;
    float *feat, *ang;
    uint4 *ap1, *ap2, *ap3, *ap4;
    float *bb1, *bb2, *bb3, *bb4;
    cudaGetSymbolAddress((void**)&b1, g_buf1);
    cudaGetSymbolAddress((void**)&b2, g_buf2);
    cudaGetSymbolAddress((void**)&b3, g_buf3);
    cudaGetSymbolAddress((void**)&feat, g_feat);
    cudaGetSymbolAddress((void**)&ang, g_ang);
    cudaGetSymbolAddress((void**)&ap1, g_ap1);
    cudaGetSymbolAddress((void**)&ap2, g_ap2);
    cudaGetSymbolAddress((void**)&ap3, g_ap3);
    cudaGetSymbolAddress((void**)&ap4, g_ap4);
    cudaGetSymbolAddress((void**)&bb1, g_bb1);
    cudaGetSymbolAddress((void**)&bb2, g_bb2);
    cudaGetSymbolAddress((void**)&bb3, g_bb3);
    cudaGetSymbolAddress((void**)&bb4, g_bb4);

    prep_all<<<128, 256>>>(
        conv1_w, conv1_b, bn1_g, bn1_b, conv2_w, conv2_b, bn2_g, bn2_b,
        conv3_w, conv3_b, bn3_g, bn3_b, conv4_w, conv4_b, bn4_g, bn4_b,
        ap1, bb1, ap2, bb2, ap3, bb3, ap4, bb4, feat);

    size_t sm1 = (size_t)4   * 144 * 4;
    size_t sm2 = (size_t)32  * 144 * 4;
    size_t sm3 = (size_t)64  * 144 * 4;   // 36864
    size_t sm4 = (size_t)128 * 144 * 4;   // 73728 > 48KB

    cudaFuncSetAttribute(conv4_mma_mean,
                         cudaFuncAttributeMaxDynamicSharedMemorySize, (int)sm4);

    // conv1: (B,4,3000) fp32 -> (B,32,3000) bf16
    conv_mma<4, 32, 0, true><<<dim3(24, B_), 256, sm1>>>(
        ap1, bb1, x, b1, 3000, 3000, 3000, 3000);
    // conv2 + pool4: -> (B,64,750) bf16 stride 752
    conv_mma<32, 64, 4, false><<<dim3(24, B_), 256, sm2>>>(
        ap2, bb2, b1, b2, 3000, 3000, 750, 752);
    // conv3 + pool4: -> (B,128,187) bf16 stride 188
    conv_mma<64, 128, 4, false><<<dim3(6, B_), 256, sm3>>>(
        ap3, bb3, b2, b3, 750, 752, 187, 188);
    // conv4 + mean (atomic) -> feat sums
    conv4_mma_mean<<<dim3(2, B_), 256, sm4>>>(ap4, bb4, b3, feat);
    // fc + ang head -> angles (B,8)
    head_kernel<<<B_, 128>>>(feat, fc_w, fc_b, ang_w, ang_b, ang);
    // quantum sim + final MLP -> (B,5)
    qsim_kernel<<<B_, 256>>>(ang, qw, h1_w, h1_b, h2_w, h2_b, out);
}